// round 10
// baseline (speedup 1.0000x reference)
#include <cuda_runtime.h>

#define BB   512
#define SS   17
#define LL   81
#define VV   13030
#define ENCD 240
#define OED  80
#define PED  60
#define IND  380     // ENC + OE + PE
#define HD   200
#define G4H  800     // 4*H
#define KPAD 592     // 37*16, padded K for gates GEMM (reordered [h|enc|oe|pe|0])

// ---------------- scratch (static device globals; no allocation) ----------------
// packed tf32 operands: uint2 = (hi, lo) interleaved
__device__ __align__(16) uint2 g_gW_p[G4H * KPAD];
__device__ __align__(16) float g_gbias[G4H];
__device__ __align__(16) uint2 g_oW_p[VV * HD];
__device__ __align__(16) uint2 g_le_p[SS * BB * ENCD];
__device__ __align__(16) uint2 g_pe_p[BB * PED];
__device__ __align__(16) uint2 g_h_p[BB * HD];
__device__ __align__(16) uint2 g_oe_p[BB * OED];
__device__ __align__(16) float g_c[BB * HD];
__device__ int      g_invalid[BB];
__device__ unsigned g_keys[2 * SS];
__device__ __align__(16) float g_scores[BB * VV];        // scratch when no scores output

// ---------------- threefry2x32 (matches jax/_src/prng.py reference) ----------------
__device__ __forceinline__ uint2 tf2x32(unsigned k0, unsigned k1,
                                        unsigned x0, unsigned x1) {
    unsigned ks2 = k0 ^ k1 ^ 0x1BD11BDAu;
    x0 += k0; x1 += k1;
#define TFR(r) { x0 += x1; x1 = __funnelshift_l(x1, x1, (r)); x1 ^= x0; }
    TFR(13) TFR(15) TFR(26) TFR(6)
    x0 += k1; x1 += ks2 + 1u;
    TFR(17) TFR(29) TFR(16) TFR(24)
    x0 += ks2; x1 += k0 + 2u;
    TFR(13) TFR(15) TFR(26) TFR(6)
    x0 += k0; x1 += k1 + 3u;
    TFR(17) TFR(29) TFR(16) TFR(24)
    x0 += k1; x1 += ks2 + 4u;
    TFR(13) TFR(15) TFR(26) TFR(6)
    x0 += ks2; x1 += k0 + 5u;
#undef TFR
    return make_uint2(x0, x1);
}

// ---------------- accurate fp32 natural log (fdlibm e_logf; fast-math-proof) ----------------
__device__ __forceinline__ float alogf(float x) {
    int ib = __float_as_int(x);
    int k  = ((ib >> 23) & 0xFF) - 126;
    float m = __int_as_float((ib & 0x007FFFFF) | 0x3F000000);
    if (m < 0.70710678f) { m = m + m; k -= 1; }
    float f = m - 1.0f;
    float s = f / (2.0f + f);
    float z = s * s;
    float w = z * z;
    float t1 = w * (0.40000972152f + w * 0.24279078841f);
    float t2 = z * (0.66666662693f + w * 0.28498786688f);
    float R  = t2 + t1;
    float hfsq = 0.5f * f * f;
    float dk = (float)k;
    return dk * 0.69313812256f - ((hfsq - (s * (hfsq + R) + dk * 9.0580006145e-06f)) - f);
}

// ---------------- tf32 helpers ----------------
__device__ __forceinline__ unsigned f2tf32(float x) {
    unsigned r;
    asm("cvt.rna.tf32.f32 %0, %1;" : "=r"(r) : "f"(x));
    return r;
}
__device__ __forceinline__ void mma_tf32(float* c, const unsigned* a, const unsigned* b) {
    asm volatile(
        "mma.sync.aligned.m16n8k8.row.col.f32.tf32.tf32.f32 "
        "{%0,%1,%2,%3}, {%4,%5,%6,%7}, {%8,%9}, {%0,%1,%2,%3};\n"
        : "+f"(c[0]), "+f"(c[1]), "+f"(c[2]), "+f"(c[3])
        : "r"(a[0]), "r"(a[1]), "r"(a[2]), "r"(a[3]), "r"(b[0]), "r"(b[1]));
}
__device__ __forceinline__ uint2 split2(float x) {
    unsigned hi = f2tf32(x);
    unsigned lo = f2tf32(x - __uint_as_float(hi));
    return make_uint2(hi, lo);
}

// cp.async 16B with zero-fill predicate
__device__ __forceinline__ void cpa16(void* sdst, const void* gsrc, bool pred) {
    unsigned saddr = (unsigned)__cvta_generic_to_shared(sdst);
    int sz = pred ? 16 : 0;
    asm volatile("cp.async.cg.shared.global [%0], [%1], 16, %2;\n"
                 :: "r"(saddr), "l"(gsrc), "r"(sz));
}

// ---------------- pack kernels (run once per launch) ----------------
// gate weights: row u' = unit*4 + gate; orig row = gate*HD + unit; k-order [h|enc|oe|pe|0pad]
__global__ __launch_bounds__(256) void pack_gw_kernel(
    const float* __restrict__ W_ih, const float* __restrict__ W_hh,
    const float* __restrict__ b_ih, const float* __restrict__ b_hh) {
    int idx = blockIdx.x * blockDim.x + threadIdx.x;
    if (idx >= G4H * KPAD) return;
    int up = idx / KPAD, k = idx - up * KPAD;
    int orig = (up & 3) * HD + (up >> 2);
    float v = 0.f;
    if (k < HD)        v = W_hh[orig * HD + k];
    else if (k < 580)  v = W_ih[orig * IND + (k - HD)];
    g_gW_p[idx] = split2(v);
    if (k == 0) g_gbias[up] = b_ih[orig] + b_hh[orig];
}

__global__ __launch_bounds__(256) void pack_ow_kernel(const float* __restrict__ out_W) {
    int idx = blockIdx.x * blockDim.x + threadIdx.x;
    if (idx >= VV * HD) return;
    g_oW_p[idx] = split2(out_W[idx]);
}

// ---------------- kernel A: precompute loc_enc(split)/power_emb(split)/state/keys ----------------
__global__ __launch_bounds__(256) void precompute_kernel(
    const float* __restrict__ enc, const int* __restrict__ loc_idxs,
    const float* __restrict__ power_1h, const float* __restrict__ power_W,
    const float* __restrict__ power_b, const float* __restrict__ master) {
    __shared__ float sM[LL * LL];
    __shared__ float sAl[SS][LL];
    __shared__ float sDen[SS];
    __shared__ int   sLoc[LL];
    int b = blockIdx.x;
    int tid = threadIdx.x;

    for (int i = tid; i < LL * LL; i += 256) sM[i] = master[i];
    if (tid < LL) sLoc[tid] = loc_idxs[b * LL + tid];
    for (int i = tid; i < HD; i += 256) {
        g_h_p[b * HD + i] = make_uint2(0u, 0u); g_c[b * HD + i] = 0.f;
    }
    for (int i = tid; i < OED; i += 256) g_oe_p[b * OED + i] = make_uint2(0u, 0u);
    if (tid < PED) {
        float acc = power_b[tid];
        for (int j = 0; j < 7; ++j) acc += power_1h[b * 7 + j] * power_W[tid * 7 + j];
        g_pe_p[b * PED + tid] = split2(acc);
    }
    if (b == 0 && tid < SS) {
        uint2 r = tf2x32(0u, 42u, 0u, (unsigned)tid);
        g_keys[2 * tid]     = r.x;
        g_keys[2 * tid + 1] = r.y;
    }
    __syncthreads();

    if (tid == 0) {
        int any = 0;
        for (int l = 0; l < LL; ++l) any |= (sLoc[l] != -1);
        g_invalid[b] = !any;
    }
    for (int e = tid; e < SS * LL; e += 256) {
        int t = e / LL, j = e % LL;
        float a = 0.f;
        for (int l = 0; l < LL; ++l) {
            int li = sLoc[l];
            if (li == t || li == -2) a += sM[l * LL + j];
        }
        sAl[t][j] = a;
    }
    __syncthreads();
    if (tid < SS) {
        float d = 0.f;
        for (int j = 0; j < LL; ++j) d += sAl[tid][j];
        sDen[tid] = d;
    }
    __syncthreads();
    for (int e = tid; e < SS * LL; e += 256) {
        int t = e / LL, j = e % LL;
        float d = sDen[t];
        sAl[t][j] = (d != 0.f) ? sAl[t][j] / d : 0.f;
    }
    __syncthreads();
    if (tid < ENCD) {
        float acc[SS];
#pragma unroll
        for (int t = 0; t < SS; ++t) acc[t] = 0.f;
        for (int l = 0; l < LL; ++l) {
            float v = enc[((size_t)b * LL + l) * ENCD + tid];
#pragma unroll
            for (int t = 0; t < SS; ++t) acc[t] += sAl[t][l] * v;
        }
#pragma unroll
        for (int t = 0; t < SS; ++t) {
            size_t o = ((size_t)t * BB + b) * ENCD + tid;
            g_le_p[o] = split2(acc[t]);
        }
    }
}

// ---------------- G1: fused gates GEMM + LSTM update (64x64 tiles, interleaved hi/lo) ----------------
// grid = (13, 8). Gate-interleaved rows: any 4-aligned 64-row window holds complete i,f,g,o quads.
// smem pitch 20 uint2/row: phase addresses 4g+tig mod 16 distinct -> conflict-free LDS.64.
struct GatesSM {
    union {
        struct {
            uint2 AP[2][64][20];
            uint2 BP[2][64][20];
        } p;
        float C[64][68];
    };
};

__global__ __launch_bounds__(256) void gates_fused_kernel(int t) {
    __shared__ GatesSM u;
    __shared__ float sBias[64];
    int tid = threadIdx.x;
    int u0 = blockIdx.x * 64, b0 = blockIdx.y * 64;
    int lane = tid & 31, warp = tid >> 5;
    int wv = warp & 1, wb = warp >> 1;         // 2 (rows) x 4 (cols)
    int g = lane >> 2, tig = lane & 3;

    if (tid < 64) {
        int up = u0 + tid;
        sBias[tid] = (up < G4H) ? g_gbias[up] : 0.f;
    }

    float acc[2][2][4];
#pragma unroll
    for (int mt = 0; mt < 2; ++mt)
#pragma unroll
        for (int nt = 0; nt < 2; ++nt)
#pragma unroll
            for (int q = 0; q < 4; ++q) acc[mt][nt][q] = 0.f;

    int row = tid >> 2, kq = (tid & 3) * 4;    // each thread: 4 uint2 = 2 cpa16 per plane
    int up = u0 + row;
    bool pA = (up < G4H);
    size_t abase = (size_t)(pA ? up : 0) * KPAD;
    int bb = b0 + row;
    const size_t le_row = (size_t)t * BB * ENCD + (size_t)bb * ENCD;

    const int NIT = KPAD / 16;                 // 37
    auto issue = [&](int it, int bi) {
        int k0 = it * 16;
        // A: packed gate weights (always in-range within KPAD; zeros pre-packed)
        cpa16(&u.p.AP[bi][row][kq],     g_gW_p + abase + k0 + kq,     pA);
        cpa16(&u.p.AP[bi][row][kq + 2], g_gW_p + abase + k0 + kq + 2, pA);
        // B: x row, k-order [h|le|oe|pe|0]; each thread's 4-k group lies in one region
        int k = k0 + kq;
        const uint2* src = g_h_p;
        bool pB = true;
        if (k < HD)                   src = g_h_p  + bb * HD  + k;
        else if (k < HD + ENCD)       src = g_le_p + le_row   + (k - HD);
        else if (k < HD + ENCD + OED) src = g_oe_p + bb * OED + (k - 440);
        else if (k < 580)             src = g_pe_p + bb * PED + (k - 520);
        else                          pB = false;
        cpa16(&u.p.BP[bi][row][kq],     src,     pB);
        cpa16(&u.p.BP[bi][row][kq + 2], src + 2, pB);
    };

    issue(0, 0);
    asm volatile("cp.async.commit_group;");
    for (int it = 0; it < NIT; ++it) {
        if (it + 1 < NIT) issue(it + 1, (it + 1) & 1);
        asm volatile("cp.async.commit_group;");
        asm volatile("cp.async.wait_group 1;");
        __syncthreads();
        int bi = it & 1;
#pragma unroll
        for (int kk = 0; kk < 16; kk += 8) {
            unsigned afh[2][4], afl[2][4], bfh[2][2], bfl[2][2];
#pragma unroll
            for (int mt = 0; mt < 2; ++mt) {
                int r = wv * 32 + mt * 16 + g;
                uint2 p0 = u.p.AP[bi][r][kk + tig];
                uint2 p1 = u.p.AP[bi][r + 8][kk + tig];
                uint2 p2 = u.p.AP[bi][r][kk + tig + 4];
                uint2 p3 = u.p.AP[bi][r + 8][kk + tig + 4];
                afh[mt][0] = p0.x; afl[mt][0] = p0.y;
                afh[mt][1] = p1.x; afl[mt][1] = p1.y;
                afh[mt][2] = p2.x; afl[mt][2] = p2.y;
                afh[mt][3] = p3.x; afl[mt][3] = p3.y;
            }
#pragma unroll
            for (int nt = 0; nt < 2; ++nt) {
                int c = wb * 16 + nt * 8 + g;
                uint2 q0 = u.p.BP[bi][c][kk + tig];
                uint2 q1 = u.p.BP[bi][c][kk + tig + 4];
                bfh[nt][0] = q0.x; bfl[nt][0] = q0.y;
                bfh[nt][1] = q1.x; bfl[nt][1] = q1.y;
            }
#pragma unroll
            for (int mt = 0; mt < 2; ++mt)
#pragma unroll
                for (int nt = 0; nt < 2; ++nt) {
                    mma_tf32(acc[mt][nt], afh[mt], bfl[nt]);
                    mma_tf32(acc[mt][nt], afl[mt], bfh[nt]);
                    mma_tf32(acc[mt][nt], afh[mt], bfh[nt]);
                }
        }
        __syncthreads();
    }

    // transpose accumulators into C[b][u'-local]
#pragma unroll
    for (int nt = 0; nt < 2; ++nt)
#pragma unroll
        for (int cc = 0; cc < 2; ++cc) {
            int bl = wb * 16 + nt * 8 + 2 * tig + cc;
#pragma unroll
            for (int mt = 0; mt < 2; ++mt)
#pragma unroll
                for (int rr = 0; rr < 2; ++rr) {
                    int vl = wv * 32 + mt * 16 + g + rr * 8;
                    u.C[bl][vl] = acc[mt][nt][rr * 2 + cc];
                }
        }
    __syncthreads();

    // fused LSTM pointwise update: one (b, unit) per work item
    int base = u0 >> 2;                         // first unit in this tile
    int nU = (G4H - u0 >= 64) ? 16 : ((G4H - u0) >> 2);
    int total = 64 * nU;
    for (int e = tid; e < total; e += 256) {
        int bl, un;
        if (nU == 16) { bl = e >> 4; un = e & 15; }
        else          { bl = e / nU; un = e - bl * nU; }
        float gi = u.C[bl][un * 4 + 0] + sBias[un * 4 + 0];
        float gf = u.C[bl][un * 4 + 1] + sBias[un * 4 + 1];
        float gg = u.C[bl][un * 4 + 2] + sBias[un * 4 + 2];
        float go = u.C[bl][un * 4 + 3] + sBias[un * 4 + 3];
        int b = b0 + bl, unit = base + un;
        float cprev = g_c[b * HD + unit];
        float si = 1.f / (1.f + expf(-gi));
        float sf = 1.f / (1.f + expf(-gf));
        float so = 1.f / (1.f + expf(-go));
        float c = sf * cprev + si * tanhf(gg);
        float h = so * tanhf(c);
        g_c[b * HD + unit] = c;
        g_h_p[b * HD + unit] = split2(h);
    }
}

// ---------------- G3: scores GEMM, cp.async double-buffered, interleaved hi/lo ----------------
struct ScoresSM {
    uint2 AP[2][128][20];   // 40960 B
    uint2 BP[2][64][20];    // 20480 B
};  // 61440 bytes

#define SCORES_SMEM (61440 + 512)

__global__ __launch_bounds__(256) void scores_mma_kernel(
    const float* __restrict__ out_b, const unsigned* __restrict__ order_masks,
    float* __restrict__ sc_base, long long pitch, long long off, int t) {
    extern __shared__ __align__(16) unsigned char dsm[];
    ScoresSM* sm = (ScoresSM*)dsm;
    float (*C)[132] = (float(*)[132])dsm;               // aliases buffers after k-loop
    float* sOutB = (float*)(dsm + sizeof(ScoresSM));
    int tid = threadIdx.x;
    int v0 = blockIdx.x * 128, b0 = blockIdx.y * 64;
    int lane = tid & 31, warp = tid >> 5;
    int wv = warp & 1, wb = warp >> 1;
    int g = lane >> 2, tig = lane & 3;

    if (tid < 128) {
        int v = v0 + tid;
        sOutB[tid] = (v < VV) ? out_b[v] : 0.f;
    }

    float acc[4][2][4];
#pragma unroll
    for (int mt = 0; mt < 4; ++mt)
#pragma unroll
        for (int nt = 0; nt < 2; ++nt)
#pragma unroll
            for (int q = 0; q < 4; ++q) acc[mt][nt][q] = 0.f;

    int arow = tid >> 1, akq = (tid & 1) * 8;   // A: 8 uint2 = 4 cpa16 per thread
    int brow = tid >> 2, bkq = (tid & 3) * 4;   // B: 4 uint2 = 2 cpa16 per thread
    int va = v0 + arow;
    size_t aoff = (va < VV) ? (size_t)va * HD : 0;
    int bb = b0 + brow;

    const int NIT = 13;                                  // 13*16 = 208 >= HD
    auto issue = [&](int it, int bi) {
        int k0 = it * 16;
#pragma unroll
        for (int j = 0; j < 4; ++j) {
            int k = k0 + akq + j * 2;
            bool pA = (va < VV) && (k < HD);
            cpa16(&sm->AP[bi][arow][akq + j * 2], g_oW_p + aoff + (pA ? k : 0), pA);
        }
#pragma unroll
        for (int j = 0; j < 2; ++j) {
            int k = k0 + bkq + j * 2;
            bool pB = (k < HD);
            cpa16(&sm->BP[bi][brow][bkq + j * 2], g_h_p + bb * HD + (pB ? k : 0), pB);
        }
    };

    issue(0, 0);
    asm volatile("cp.async.commit_group;");
    for (int it = 0; it < NIT; ++it) {
        if (it + 1 < NIT) issue(it + 1, (it + 1) & 1);
        asm volatile("cp.async.commit_group;");
        asm volatile("cp.async.wait_group 1;");
        __syncthreads();
        int bi = it & 1;
#pragma unroll
        for (int kk = 0; kk < 16; kk += 8) {
            unsigned afh[4][4], afl[4][4], bfh[2][2], bfl[2][2];
#pragma unroll
            for (int mt = 0; mt < 4; ++mt) {
                int r = wv * 64 + mt * 16 + g;
                uint2 p0 = sm->AP[bi][r][kk + tig];
                uint2 p1 = sm->AP[bi][r + 8][kk + tig];
                uint2 p2 = sm->AP[bi][r][kk + tig + 4];
                uint2 p3 = sm->AP[bi][r + 8][kk + tig + 4];
                afh[mt][0] = p0.x; afl[mt][0] = p0.y;
                afh[mt][1] = p1.x; afl[mt][1] = p1.y;
                afh[mt][2] = p2.x; afl[mt][2] = p2.y;
                afh[mt][3] = p3.x; afl[mt][3] = p3.y;
            }
#pragma unroll
            for (int nt = 0; nt < 2; ++nt) {
                int c = wb * 16 + nt * 8 + g;
                uint2 q0 = sm->BP[bi][c][kk + tig];
                uint2 q1 = sm->BP[bi][c][kk + tig + 4];
                bfh[nt][0] = q0.x; bfl[nt][0] = q0.y;
                bfh[nt][1] = q1.x; bfl[nt][1] = q1.y;
            }
#pragma unroll
            for (int mt = 0; mt < 4; ++mt)
#pragma unroll
                for (int nt = 0; nt < 2; ++nt) {
                    mma_tf32(acc[mt][nt], afh[mt], bfl[nt]);
                    mma_tf32(acc[mt][nt], afl[mt], bfh[nt]);
                    mma_tf32(acc[mt][nt], afh[mt], bfh[nt]);
                }
        }
        __syncthreads();
    }

    // transpose accumulators through smem (aliases the now-idle buffers)
#pragma unroll
    for (int nt = 0; nt < 2; ++nt)
#pragma unroll
        for (int cc = 0; cc < 2; ++cc) {
            int bl = wb * 16 + nt * 8 + 2 * tig + cc;
#pragma unroll
            for (int mt = 0; mt < 4; ++mt)
#pragma unroll
                for (int rr = 0; rr < 2; ++rr) {
                    int vl = wv * 64 + mt * 16 + g + rr * 8;
                    C[bl][vl] = acc[mt][nt][rr * 2 + cc];
                }
        }
    __syncthreads();

    // coalesced float2 store with bias + mask
    for (int e = tid; e < 64 * 64; e += 256) {
        int bl = e >> 6, v2 = e & 63;
        int b = b0 + bl;
        int v = v0 + v2 * 2;
        if (v >= VV) continue;
        float2 c = *(float2*)&C[bl][v2 * 2];
        c.x += sOutB[v2 * 2];
        c.y += sOutB[v2 * 2 + 1];
        int inv = g_invalid[b];
        uint2 m2 = *(const uint2*)(order_masks + ((size_t)b * SS + t) * VV + v);
        bool ma = inv || (m2.x != 0u);
        bool mb = inv || (m2.y != 0u);
        float2 r;
        r.x = fminf(c.x, ma ? 9.0e8f : -1.0e8f);
        r.y = fminf(c.y, mb ? 9.0e8f : -1.0e8f);
        *(float2*)(sc_base + (long long)b * pitch + off + v) = r;
    }
}

// ---------------- G4: sample kernel — ballot-compacted gumbel argmax + finish ----------------
__device__ __forceinline__ float gproc(float sm, int vv, int b,
                                       unsigned k1t, unsigned k2t,
                                       float rb, unsigned long long& best) {
    uint2 r = tf2x32(k1t, k2t, 0u, (unsigned)(b * VV + vv));
    unsigned bits = r.x ^ r.y;
    float uf = __uint_as_float((bits >> 9) | 0x3F800000u) - 1.0f;
    uf = fmaxf(uf + 1.17549435e-38f, 1.17549435e-38f);
    float lnu_lo = fmaf((float)__float_as_int(uf), 8.2629582e-8f, -88.029694f);
    float e_min = -lnu_lo - 0.0605f;
    float gub = 3.0e38f;
    if (e_min > 1.17549435e-38f) {
        float lne_lo = fmaf((float)__float_as_int(e_min), 8.2629582e-8f, -88.029694f);
        gub = -lne_lo + 1.0e-3f;
    }
    if (sm + gub < rb) return -3.0e38f;
    float gum = -alogf(-alogf(uf));
    float cv = sm + gum;
    unsigned ub = __float_as_uint(cv);
    ub = (ub & 0x80000000u) ? ~ub : (ub | 0x80000000u);
    unsigned long long packed = ((unsigned long long)ub << 32) | (unsigned)(~(unsigned)vv);
    if (packed > best) best = packed;
    return cv;
}

__global__ __launch_bounds__(256) void sample_kernel(
    const float* __restrict__ sc_base, long long pitch, long long off,
    const float* __restrict__ order_embedding, float* __restrict__ idx_out, int t) {
    int b = blockIdx.x;
    const float* row = sc_base + (long long)b * pitch + off;
    int tid = threadIdx.x, warp = tid >> 5, lane = tid & 31;
    __shared__ unsigned short qv[8][64];
    __shared__ float qs[8][64];
    __shared__ unsigned long long wbest[8];
    __shared__ int sidx;
    unsigned k1t = g_keys[2 * t], k2t = g_keys[2 * t + 1];
    const int SEG = 1632;
    int s0 = warp * SEG;
    int s1 = min(s0 + SEG, VV);
    unsigned long long best = 0ULL;
    float rb = -3.0e38f;
    int qh = 0, qt = 0;

    for (int v0 = s0; v0 < s1; v0 += 32) {
        int v = v0 + lane;
        float sv = (v < s1) ? row[v] : -1.0e8f;
        bool cand = (v < s1) && (sv != -1.0e8f);
        unsigned mk = __ballot_sync(0xffffffffu, cand);
        int rank = __popc(mk & ((1u << lane) - 1u));
        if (cand) {
            int p = (qt + rank) & 63;
            qv[warp][p] = (unsigned short)v;
            qs[warp][p] = sv;
        }
        qt += __popc(mk);
        while (qt - qh >= 32) {
            __syncwarp();
            int p = (qh + lane) & 63;
            int vv = qv[warp][p];
            float smv = qs[warp][p];
            __syncwarp();
            qh += 32;
            float cv = gproc(smv, vv, b, k1t, k2t, rb, best);
#pragma unroll
            for (int o = 16; o; o >>= 1)
                cv = fmaxf(cv, __shfl_xor_sync(0xffffffffu, cv, o));
            rb = fmaxf(rb, cv);
        }
    }
    {
        int rem = qt - qh;
        __syncwarp();
        if (lane < rem) {
            int p = (qh + lane) & 63;
            int vv = qv[warp][p];
            float smv = qs[warp][p];
            (void)gproc(smv, vv, b, k1t, k2t, rb, best);
        }
    }
#pragma unroll
    for (int o = 16; o; o >>= 1) {
        unsigned long long ob = __shfl_xor_sync(0xffffffffu, best, o);
        if (ob > best) best = ob;
    }
    if (lane == 0) wbest[warp] = best;
    __syncthreads();
    if (tid == 0) {
        unsigned long long bb = 0ULL;
#pragma unroll
        for (int w = 0; w < 8; ++w) bb = (wbest[w] > bb) ? wbest[w] : bb;
        int idx = (bb == 0ULL) ? 0 : (int)(~(unsigned)(bb & 0xFFFFFFFFu));
        if (idx < 0) idx = 0;
        if (idx >= VV) idx = VV - 1;
        sidx = idx;
        if (idx_out) idx_out[b * SS + t] = (float)idx;
    }
    __syncthreads();
    if (tid < OED) {
        float val = order_embedding[(size_t)sidx * OED + tid];
        g_oe_p[b * OED + tid] = split2(val);
    }
}

// ---------------- launch ----------------
extern "C" void kernel_launch(void* const* d_in, const int* in_sizes, int n_in,
                              void* d_out, int out_size) {
    const float*    enc        = (const float*)d_in[0];
    const int*      loc_idxs   = (const int*)d_in[2];
    const unsigned* ord_masks  = (const unsigned*)d_in[3];
    const float*    power_1h   = (const float*)d_in[4];
    const float*    order_emb  = (const float*)d_in[5];
    const float*    power_W    = (const float*)d_in[6];
    const float*    power_b    = (const float*)d_in[7];
    const float*    W_ih       = (const float*)d_in[8];
    const float*    W_hh       = (const float*)d_in[9];
    const float*    b_ih       = (const float*)d_in[10];
    const float*    b_hh       = (const float*)d_in[11];
    const float*    out_W      = (const float*)d_in[12];
    const float*    out_b      = (const float*)d_in[13];
    const float*    master     = (const float*)d_in[14];

    float* out = (float*)d_out;
    float* idx_out = nullptr;
    float* scores_out = nullptr;
    const long long NSC = (long long)BB * SS * VV;
    if ((long long)out_size == NSC + (long long)BB * SS) { idx_out = out; scores_out = out + BB * SS; }
    else if ((long long)out_size == NSC)                 { scores_out = out; }
    else if (out_size == BB * SS)                        { idx_out = out; }
    else { scores_out = out; }

    float* g_scores_ptr = nullptr;
    cudaGetSymbolAddress((void**)&g_scores_ptr, g_scores);
    float*    sc_base = scores_out ? scores_out : g_scores_ptr;
    long long pitch   = scores_out ? (long long)SS * VV : (long long)VV;

    cudaFuncSetAttribute(scores_mma_kernel,
                         cudaFuncAttributeMaxDynamicSharedMemorySize, SCORES_SMEM);

    precompute_kernel<<<BB, 256>>>(enc, loc_idxs, power_1h, power_W, power_b, master);
    pack_gw_kernel<<<(G4H * KPAD + 255) / 256, 256>>>(W_ih, W_hh, b_ih, b_hh);
    pack_ow_kernel<<<(VV * HD + 255) / 256, 256>>>(out_W);

    dim3 g1grid((G4H + 63) / 64, BB / 64);           // 13 x 8 = 104 blocks
    dim3 g3grid((VV + 127) / 128, BB / 64);          // 102 x 8
    for (int t = 0; t < SS; ++t) {
        long long off = scores_out ? (long long)t * VV : 0;
        gates_fused_kernel<<<g1grid, 256>>>(t);
        scores_mma_kernel<<<g3grid, 256, SCORES_SMEM>>>(out_b, ord_masks, sc_base, pitch, off, t);
        sample_kernel<<<BB, 256>>>(sc_base, pitch, off, order_emb, idx_out, t);
    }
}

// round 11
// speedup vs baseline: 1.0045x; 1.0045x over previous
#include <cuda_runtime.h>

#define BB   512
#define SS   17
#define LL   81
#define VV   13030
#define ENCD 240
#define OED  80
#define PED  60
#define IND  380     // ENC + OE + PE
#define HD   200
#define G4H  800     // 4*H
#define KPAD 592     // 37*16, padded K for gates GEMM (reordered [h|enc|oe|pe|0])

// ---------------- scratch (static device globals; no allocation) ----------------
__device__ __align__(16) unsigned g_gW_hi[G4H * KPAD];   // permuted+packed gate weights
__device__ __align__(16) unsigned g_gW_lo[G4H * KPAD];
__device__ __align__(16) float    g_gbias[G4H];
__device__ __align__(16) unsigned g_oW_hi[VV * HD];
__device__ __align__(16) unsigned g_oW_lo[VV * HD];
__device__ __align__(16) unsigned g_le_hi[SS * BB * ENCD];
__device__ __align__(16) unsigned g_le_lo[SS * BB * ENCD];
__device__ __align__(16) unsigned g_pe_hi[BB * PED];
__device__ __align__(16) unsigned g_pe_lo[BB * PED];
__device__ __align__(16) unsigned g_h_hi[BB * HD];
__device__ __align__(16) unsigned g_h_lo[BB * HD];
__device__ __align__(16) unsigned g_oe_hi[BB * OED];
__device__ __align__(16) unsigned g_oe_lo[BB * OED];
__device__ __align__(16) float    g_c[BB * HD];
__device__ int      g_invalid[BB];
__device__ unsigned g_keys[2 * SS];
__device__ __align__(16) float g_scores[BB * VV];        // scratch when no scores output

// ---------------- threefry2x32 (matches jax/_src/prng.py reference) ----------------
__device__ __forceinline__ uint2 tf2x32(unsigned k0, unsigned k1,
                                        unsigned x0, unsigned x1) {
    unsigned ks2 = k0 ^ k1 ^ 0x1BD11BDAu;
    x0 += k0; x1 += k1;
#define TFR(r) { x0 += x1; x1 = __funnelshift_l(x1, x1, (r)); x1 ^= x0; }
    TFR(13) TFR(15) TFR(26) TFR(6)
    x0 += k1; x1 += ks2 + 1u;
    TFR(17) TFR(29) TFR(16) TFR(24)
    x0 += ks2; x1 += k0 + 2u;
    TFR(13) TFR(15) TFR(26) TFR(6)
    x0 += k0; x1 += k1 + 3u;
    TFR(17) TFR(29) TFR(16) TFR(24)
    x0 += k1; x1 += ks2 + 4u;
    TFR(13) TFR(15) TFR(26) TFR(6)
    x0 += ks2; x1 += k0 + 5u;
#undef TFR
    return make_uint2(x0, x1);
}

// ---------------- accurate fp32 natural log (fdlibm e_logf; fast-math-proof) ----------------
__device__ __forceinline__ float alogf(float x) {
    int ib = __float_as_int(x);
    int k  = ((ib >> 23) & 0xFF) - 126;
    float m = __int_as_float((ib & 0x007FFFFF) | 0x3F000000);
    if (m < 0.70710678f) { m = m + m; k -= 1; }
    float f = m - 1.0f;
    float s = f / (2.0f + f);
    float z = s * s;
    float w = z * z;
    float t1 = w * (0.40000972152f + w * 0.24279078841f);
    float t2 = z * (0.66666662693f + w * 0.28498786688f);
    float R  = t2 + t1;
    float hfsq = 0.5f * f * f;
    float dk = (float)k;
    return dk * 0.69313812256f - ((hfsq - (s * (hfsq + R) + dk * 9.0580006145e-06f)) - f);
}

// ---------------- tf32 helpers ----------------
__device__ __forceinline__ unsigned f2tf32(float x) {
    unsigned r;
    asm("cvt.rna.tf32.f32 %0, %1;" : "=r"(r) : "f"(x));
    return r;
}
__device__ __forceinline__ void mma_tf32(float* c, const unsigned* a, const unsigned* b) {
    asm volatile(
        "mma.sync.aligned.m16n8k8.row.col.f32.tf32.tf32.f32 "
        "{%0,%1,%2,%3}, {%4,%5,%6,%7}, {%8,%9}, {%0,%1,%2,%3};\n"
        : "+f"(c[0]), "+f"(c[1]), "+f"(c[2]), "+f"(c[3])
        : "r"(a[0]), "r"(a[1]), "r"(a[2]), "r"(a[3]), "r"(b[0]), "r"(b[1]));
}
__device__ __forceinline__ void split1(float x, unsigned& hi, unsigned& lo) {
    hi = f2tf32(x);
    lo = f2tf32(x - __uint_as_float(hi));
}

// cp.async 16B with zero-fill predicate
__device__ __forceinline__ void cpa16(void* sdst, const void* gsrc, bool pred) {
    unsigned saddr = (unsigned)__cvta_generic_to_shared(sdst);
    int sz = pred ? 16 : 0;
    asm volatile("cp.async.cg.shared.global [%0], [%1], 16, %2;\n"
                 :: "r"(saddr), "l"(gsrc), "r"(sz));
}

// ---------------- pack kernels (run once per launch) ----------------
// gate weights: row u' = unit*4 + gate; orig row = gate*HD + unit; k-order [h|enc|oe|pe|0pad]
__global__ __launch_bounds__(256) void pack_gw_kernel(
    const float* __restrict__ W_ih, const float* __restrict__ W_hh,
    const float* __restrict__ b_ih, const float* __restrict__ b_hh) {
    int idx = blockIdx.x * blockDim.x + threadIdx.x;
    if (idx >= G4H * KPAD) return;
    int up = idx / KPAD, k = idx - up * KPAD;
    int orig = (up & 3) * HD + (up >> 2);
    float v = 0.f;
    if (k < HD)        v = W_hh[orig * HD + k];
    else if (k < 580)  v = W_ih[orig * IND + (k - HD)];
    unsigned hi, lo; split1(v, hi, lo);
    g_gW_hi[idx] = hi; g_gW_lo[idx] = lo;
    if (k == 0) g_gbias[up] = b_ih[orig] + b_hh[orig];
}

__global__ __launch_bounds__(256) void pack_ow_kernel(const float* __restrict__ out_W) {
    int idx = blockIdx.x * blockDim.x + threadIdx.x;
    if (idx >= VV * HD) return;
    unsigned hi, lo; split1(out_W[idx], hi, lo);
    g_oW_hi[idx] = hi; g_oW_lo[idx] = lo;
}

// ---------------- kernel A: precompute loc_enc(split)/power_emb(split)/state/keys ----------------
__global__ __launch_bounds__(256) void precompute_kernel(
    const float* __restrict__ enc, const int* __restrict__ loc_idxs,
    const float* __restrict__ power_1h, const float* __restrict__ power_W,
    const float* __restrict__ power_b, const float* __restrict__ master) {
    __shared__ float sM[LL * LL];
    __shared__ float sAl[SS][LL];
    __shared__ float sDen[SS];
    __shared__ int   sLoc[LL];
    int b = blockIdx.x;
    int tid = threadIdx.x;

    for (int i = tid; i < LL * LL; i += 256) sM[i] = master[i];
    if (tid < LL) sLoc[tid] = loc_idxs[b * LL + tid];
    for (int i = tid; i < HD; i += 256) {
        g_h_hi[b * HD + i] = 0u; g_h_lo[b * HD + i] = 0u; g_c[b * HD + i] = 0.f;
    }
    for (int i = tid; i < OED; i += 256) { g_oe_hi[b * OED + i] = 0u; g_oe_lo[b * OED + i] = 0u; }
    if (tid < PED) {
        float acc = power_b[tid];
        for (int j = 0; j < 7; ++j) acc += power_1h[b * 7 + j] * power_W[tid * 7 + j];
        unsigned hi, lo; split1(acc, hi, lo);
        g_pe_hi[b * PED + tid] = hi; g_pe_lo[b * PED + tid] = lo;
    }
    if (b == 0 && tid < SS) {
        uint2 r = tf2x32(0u, 42u, 0u, (unsigned)tid);
        g_keys[2 * tid]     = r.x;
        g_keys[2 * tid + 1] = r.y;
    }
    __syncthreads();

    if (tid == 0) {
        int any = 0;
        for (int l = 0; l < LL; ++l) any |= (sLoc[l] != -1);
        g_invalid[b] = !any;
    }
    for (int e = tid; e < SS * LL; e += 256) {
        int t = e / LL, j = e % LL;
        float a = 0.f;
        for (int l = 0; l < LL; ++l) {
            int li = sLoc[l];
            if (li == t || li == -2) a += sM[l * LL + j];
        }
        sAl[t][j] = a;
    }
    __syncthreads();
    if (tid < SS) {
        float d = 0.f;
        for (int j = 0; j < LL; ++j) d += sAl[tid][j];
        sDen[tid] = d;
    }
    __syncthreads();
    for (int e = tid; e < SS * LL; e += 256) {
        int t = e / LL, j = e % LL;
        float d = sDen[t];
        sAl[t][j] = (d != 0.f) ? sAl[t][j] / d : 0.f;
    }
    __syncthreads();
    if (tid < ENCD) {
        float acc[SS];
#pragma unroll
        for (int t = 0; t < SS; ++t) acc[t] = 0.f;
        for (int l = 0; l < LL; ++l) {
            float v = enc[((size_t)b * LL + l) * ENCD + tid];
#pragma unroll
            for (int t = 0; t < SS; ++t) acc[t] += sAl[t][l] * v;
        }
#pragma unroll
        for (int t = 0; t < SS; ++t) {
            unsigned hi, lo; split1(acc[t], hi, lo);
            size_t o = ((size_t)t * BB + b) * ENCD + tid;
            g_le_hi[o] = hi; g_le_lo[o] = lo;
        }
    }
}

// ---------------- G1: fused gates GEMM + LSTM update (64x64 tiles, cp.async pipeline) ----------------
// grid = (13, 8). Gate-interleaved rows: any 4-aligned 64-row window holds complete i,f,g,o quads.
struct GatesSM {
    union {
        struct {
            unsigned AH[2][64][20];
            unsigned AL[2][64][20];
            unsigned BH[2][64][20];
            unsigned BL[2][64][20];
        } p;
        float C[64][68];
    };
};

__global__ __launch_bounds__(256) void gates_fused_kernel(int t) {
    __shared__ GatesSM u;
    __shared__ float sBias[64];
    int tid = threadIdx.x;
    int u0 = blockIdx.x * 64, b0 = blockIdx.y * 64;
    int lane = tid & 31, warp = tid >> 5;
    int wv = warp & 1, wb = warp >> 1;         // 2 (rows) x 4 (cols)
    int g = lane >> 2, tig = lane & 3;

    if (tid < 64) {
        int up = u0 + tid;
        sBias[tid] = (up < G4H) ? g_gbias[up] : 0.f;
    }

    float acc[2][2][4];
#pragma unroll
    for (int mt = 0; mt < 2; ++mt)
#pragma unroll
        for (int nt = 0; nt < 2; ++nt)
#pragma unroll
            for (int q = 0; q < 4; ++q) acc[mt][nt][q] = 0.f;

    int arow = tid >> 2, akp = (tid & 3) * 4;  // 64 rows x 16k, 1 cpa16 per plane per thread
    int brow = arow,    bkp = akp;
    int up = u0 + arow;
    bool pA = (up < G4H);
    size_t abase = (size_t)(pA ? up : 0) * KPAD;
    int bb = b0 + brow;
    const size_t le_row = (size_t)t * BB * ENCD + (size_t)bb * ENCD;

    const int NIT = KPAD / 16;                 // 37
    auto issue = [&](int it, int bi) {
        int k0 = it * 16;
        // A: packed gate weights
        cpa16(&u.p.AH[bi][arow][akp], g_gW_hi + abase + k0 + akp, pA);
        cpa16(&u.p.AL[bi][arow][akp], g_gW_lo + abase + k0 + akp, pA);
        // B: x row, k-order [h|le|oe|pe|0]
        int k = k0 + bkp;
        const unsigned *sh = g_h_hi, *sl = g_h_lo;
        bool pB = true;
        if (k < HD)                   { sh = g_h_hi + bb * HD + k;            sl = g_h_lo + bb * HD + k; }
        else if (k < HD + ENCD)       { sh = g_le_hi + le_row + (k - HD);     sl = g_le_lo + le_row + (k - HD); }
        else if (k < HD + ENCD + OED) { sh = g_oe_hi + bb * OED + (k - 440);  sl = g_oe_lo + bb * OED + (k - 440); }
        else if (k < 580)             { sh = g_pe_hi + bb * PED + (k - 520);  sl = g_pe_lo + bb * PED + (k - 520); }
        else                          { pB = false; }
        cpa16(&u.p.BH[bi][brow][bkp], sh, pB);
        cpa16(&u.p.BL[bi][brow][bkp], sl, pB);
    };

    issue(0, 0);
    asm volatile("cp.async.commit_group;");
    for (int it = 0; it < NIT; ++it) {
        if (it + 1 < NIT) issue(it + 1, (it + 1) & 1);
        asm volatile("cp.async.commit_group;");
        asm volatile("cp.async.wait_group 1;");
        __syncthreads();
        int bi = it & 1;
#pragma unroll
        for (int kk = 0; kk < 16; kk += 8) {
            unsigned afh[2][4], afl[2][4], bfh[2][2], bfl[2][2];
#pragma unroll
            for (int mt = 0; mt < 2; ++mt) {
                int r = wv * 32 + mt * 16 + g;
                afh[mt][0] = u.p.AH[bi][r][kk + tig];
                afh[mt][1] = u.p.AH[bi][r + 8][kk + tig];
                afh[mt][2] = u.p.AH[bi][r][kk + tig + 4];
                afh[mt][3] = u.p.AH[bi][r + 8][kk + tig + 4];
                afl[mt][0] = u.p.AL[bi][r][kk + tig];
                afl[mt][1] = u.p.AL[bi][r + 8][kk + tig];
                afl[mt][2] = u.p.AL[bi][r][kk + tig + 4];
                afl[mt][3] = u.p.AL[bi][r + 8][kk + tig + 4];
            }
#pragma unroll
            for (int nt = 0; nt < 2; ++nt) {
                int c = wb * 16 + nt * 8 + g;
                bfh[nt][0] = u.p.BH[bi][c][kk + tig];
                bfh[nt][1] = u.p.BH[bi][c][kk + tig + 4];
                bfl[nt][0] = u.p.BL[bi][c][kk + tig];
                bfl[nt][1] = u.p.BL[bi][c][kk + tig + 4];
            }
#pragma unroll
            for (int mt = 0; mt < 2; ++mt)
#pragma unroll
                for (int nt = 0; nt < 2; ++nt) {
                    mma_tf32(acc[mt][nt], afh[mt], bfl[nt]);
                    mma_tf32(acc[mt][nt], afl[mt], bfh[nt]);
                    mma_tf32(acc[mt][nt], afh[mt], bfh[nt]);
                }
        }
        __syncthreads();
    }

    // transpose accumulators into C[b][u'-local]
#pragma unroll
    for (int nt = 0; nt < 2; ++nt)
#pragma unroll
        for (int cc = 0; cc < 2; ++cc) {
            int bl = wb * 16 + nt * 8 + 2 * tig + cc;
#pragma unroll
            for (int mt = 0; mt < 2; ++mt)
#pragma unroll
                for (int rr = 0; rr < 2; ++rr) {
                    int vl = wv * 32 + mt * 16 + g + rr * 8;
                    u.C[bl][vl] = acc[mt][nt][rr * 2 + cc];
                }
        }
    __syncthreads();

    // fused LSTM pointwise update: one (b, unit) per work item
    int base = u0 >> 2;                         // first unit in this tile
    int nU = (G4H - u0 >= 64) ? 16 : ((G4H - u0) >> 2);
    int total = 64 * nU;
    for (int e = tid; e < total; e += 256) {
        int bl, un;
        if (nU == 16) { bl = e >> 4; un = e & 15; }
        else          { bl = e / nU; un = e - bl * nU; }
        float gi = u.C[bl][un * 4 + 0] + sBias[un * 4 + 0];
        float gf = u.C[bl][un * 4 + 1] + sBias[un * 4 + 1];
        float gg = u.C[bl][un * 4 + 2] + sBias[un * 4 + 2];
        float go = u.C[bl][un * 4 + 3] + sBias[un * 4 + 3];
        int b = b0 + bl, unit = base + un;
        float cprev = g_c[b * HD + unit];
        float si = 1.f / (1.f + expf(-gi));
        float sf = 1.f / (1.f + expf(-gf));
        float so = 1.f / (1.f + expf(-go));
        float c = sf * cprev + si * tanhf(gg);
        float h = so * tanhf(c);
        g_c[b * HD + unit] = c;
        unsigned hh, hl; split1(h, hh, hl);
        g_h_hi[b * HD + unit] = hh;
        g_h_lo[b * HD + unit] = hl;
    }
}

// ---------------- G3: scores GEMM, 128v x 128b block, 64x32 warp tile, cp.async pipeline ----------------
struct ScoresSM {
    unsigned AH[2][128][20];   // 20480 B
    unsigned AL[2][128][20];
    unsigned BH[2][128][20];
    unsigned BL[2][128][20];
};  // 81920 bytes

#define SCORES_SMEM (81920 + 512)

__global__ __launch_bounds__(256) void scores_mma_kernel(
    const float* __restrict__ out_b, const unsigned* __restrict__ order_masks,
    float* __restrict__ sc_base, long long pitch, long long off, int t) {
    extern __shared__ __align__(16) unsigned char dsm[];
    ScoresSM* sm = (ScoresSM*)dsm;
    float (*C)[132] = (float(*)[132])dsm;               // aliases buffers after k-loop
    float* sOutB = (float*)(dsm + sizeof(ScoresSM));
    int tid = threadIdx.x;
    int v0 = blockIdx.x * 128, b0 = blockIdx.y * 128;
    int lane = tid & 31, warp = tid >> 5;
    int wv = warp & 1, wb = warp >> 1;                  // 2 v-halves x 4 b-groups
    int g = lane >> 2, tig = lane & 3;

    if (tid < 128) {
        int v = v0 + tid;
        sOutB[tid] = (v < VV) ? out_b[v] : 0.f;
    }

    float acc[4][4][4];
#pragma unroll
    for (int mt = 0; mt < 4; ++mt)
#pragma unroll
        for (int nt = 0; nt < 4; ++nt)
#pragma unroll
            for (int q = 0; q < 4; ++q) acc[mt][nt][q] = 0.f;

    int arow = tid >> 1, akq = (tid & 1) * 8;           // A & B: 128 rows, 2 threads/row
    int va = v0 + arow;
    size_t aoff = (va < VV) ? (size_t)va * HD : 0;
    int bb = b0 + arow;                                  // b row for B loads

    const int NIT = 13;                                  // 13*16 = 208 >= HD
    auto issue = [&](int it, int bi) {
        int k0 = it * 16;
        int k0q = k0 + akq, k1q = k0 + akq + 4;
        bool pA0 = (va < VV) && (k0q < HD);
        bool pA1 = (va < VV) && (k1q < HD);
        int cA0 = pA0 ? k0q : 0, cA1 = pA1 ? k1q : 0;
        cpa16(&sm->AH[bi][arow][akq],     g_oW_hi + aoff + cA0, pA0);
        cpa16(&sm->AH[bi][arow][akq + 4], g_oW_hi + aoff + cA1, pA1);
        cpa16(&sm->AL[bi][arow][akq],     g_oW_lo + aoff + cA0, pA0);
        cpa16(&sm->AL[bi][arow][akq + 4], g_oW_lo + aoff + cA1, pA1);
        bool pB0 = (k0q < HD), pB1 = (k1q < HD);
        int cB0 = pB0 ? k0q : 0, cB1 = pB1 ? k1q : 0;
        cpa16(&sm->BH[bi][arow][akq],     g_h_hi + bb * HD + cB0, pB0);
        cpa16(&sm->BH[bi][arow][akq + 4], g_h_hi + bb * HD + cB1, pB1);
        cpa16(&sm->BL[bi][arow][akq],     g_h_lo + bb * HD + cB0, pB0);
        cpa16(&sm->BL[bi][arow][akq + 4], g_h_lo + bb * HD + cB1, pB1);
    };

    issue(0, 0);
    asm volatile("cp.async.commit_group;");
    for (int it = 0; it < NIT; ++it) {
        if (it + 1 < NIT) issue(it + 1, (it + 1) & 1);
        asm volatile("cp.async.commit_group;");
        asm volatile("cp.async.wait_group 1;");
        __syncthreads();
        int bi = it & 1;
#pragma unroll
        for (int kk = 0; kk < 16; kk += 8) {
            unsigned afh[4][4], afl[4][4], bfh[4][2], bfl[4][2];
#pragma unroll
            for (int mt = 0; mt < 4; ++mt) {
                int r = wv * 64 + mt * 16 + g;
                afh[mt][0] = sm->AH[bi][r][kk + tig];
                afh[mt][1] = sm->AH[bi][r + 8][kk + tig];
                afh[mt][2] = sm->AH[bi][r][kk + tig + 4];
                afh[mt][3] = sm->AH[bi][r + 8][kk + tig + 4];
                afl[mt][0] = sm->AL[bi][r][kk + tig];
                afl[mt][1] = sm->AL[bi][r + 8][kk + tig];
                afl[mt][2] = sm->AL[bi][r][kk + tig + 4];
                afl[mt][3] = sm->AL[bi][r + 8][kk + tig + 4];
            }
#pragma unroll
            for (int nt = 0; nt < 4; ++nt) {
                int c = wb * 32 + nt * 8 + g;
                bfh[nt][0] = sm->BH[bi][c][kk + tig];
                bfh[nt][1] = sm->BH[bi][c][kk + tig + 4];
                bfl[nt][0] = sm->BL[bi][c][kk + tig];
                bfl[nt][1] = sm->BL[bi][c][kk + tig + 4];
            }
#pragma unroll
            for (int mt = 0; mt < 4; ++mt)
#pragma unroll
                for (int nt = 0; nt < 4; ++nt) {
                    mma_tf32(acc[mt][nt], afh[mt], bfl[nt]);
                    mma_tf32(acc[mt][nt], afl[mt], bfh[nt]);
                    mma_tf32(acc[mt][nt], afh[mt], bfh[nt]);
                }
        }
        __syncthreads();
    }

    // transpose accumulators through smem (aliases the now-idle buffers): C[128][132]
#pragma unroll
    for (int nt = 0; nt < 4; ++nt)
#pragma unroll
        for (int cc = 0; cc < 2; ++cc) {
            int bl = wb * 32 + nt * 8 + 2 * tig + cc;
#pragma unroll
            for (int mt = 0; mt < 4; ++mt)
#pragma unroll
                for (int rr = 0; rr < 2; ++rr) {
                    int vl = wv * 64 + mt * 16 + g + rr * 8;
                    C[bl][vl] = acc[mt][nt][rr * 2 + cc];
                }
        }
    __syncthreads();

    // coalesced float2 store with bias + mask (128 b rows x 64 float2)
    for (int e = tid; e < 128 * 64; e += 256) {
        int bl = e >> 6, v2 = e & 63;
        int b = b0 + bl;
        int v = v0 + v2 * 2;
        if (v >= VV) continue;
        float2 c = *(float2*)&C[bl][v2 * 2];
        c.x += sOutB[v2 * 2];
        c.y += sOutB[v2 * 2 + 1];
        int inv = g_invalid[b];
        uint2 m2 = *(const uint2*)(order_masks + ((size_t)b * SS + t) * VV + v);
        bool ma = inv || (m2.x != 0u);
        bool mb = inv || (m2.y != 0u);
        float2 r;
        r.x = fminf(c.x, ma ? 9.0e8f : -1.0e8f);
        r.y = fminf(c.y, mb ? 9.0e8f : -1.0e8f);
        *(float2*)(sc_base + (long long)b * pitch + off + v) = r;
    }
}

// ---------------- G4: sample kernel — ballot-compacted gumbel argmax + finish ----------------
__device__ __forceinline__ float gproc(float sm, int vv, int b,
                                       unsigned k1t, unsigned k2t,
                                       float rb, unsigned long long& best) {
    uint2 r = tf2x32(k1t, k2t, 0u, (unsigned)(b * VV + vv));
    unsigned bits = r.x ^ r.y;
    float uf = __uint_as_float((bits >> 9) | 0x3F800000u) - 1.0f;
    uf = fmaxf(uf + 1.17549435e-38f, 1.17549435e-38f);
    float lnu_lo = fmaf((float)__float_as_int(uf), 8.2629582e-8f, -88.029694f);
    float e_min = -lnu_lo - 0.0605f;
    float gub = 3.0e38f;
    if (e_min > 1.17549435e-38f) {
        float lne_lo = fmaf((float)__float_as_int(e_min), 8.2629582e-8f, -88.029694f);
        gub = -lne_lo + 1.0e-3f;
    }
    if (sm + gub < rb) return -3.0e38f;
    float gum = -alogf(-alogf(uf));
    float cv = sm + gum;
    unsigned ub = __float_as_uint(cv);
    ub = (ub & 0x80000000u) ? ~ub : (ub | 0x80000000u);
    unsigned long long packed = ((unsigned long long)ub << 32) | (unsigned)(~(unsigned)vv);
    if (packed > best) best = packed;
    return cv;
}

__global__ __launch_bounds__(256) void sample_kernel(
    const float* __restrict__ sc_base, long long pitch, long long off,
    const float* __restrict__ order_embedding, float* __restrict__ idx_out, int t) {
    int b = blockIdx.x;
    const float* row = sc_base + (long long)b * pitch + off;
    int tid = threadIdx.x, warp = tid >> 5, lane = tid & 31;
    __shared__ unsigned short qv[8][64];
    __shared__ float qs[8][64];
    __shared__ unsigned long long wbest[8];
    __shared__ int sidx;
    unsigned k1t = g_keys[2 * t], k2t = g_keys[2 * t + 1];
    const int SEG = 1632;
    int s0 = warp * SEG;
    int s1 = min(s0 + SEG, VV);
    unsigned long long best = 0ULL;
    float rb = -3.0e38f;
    int qh = 0, qt = 0;

    for (int v0 = s0; v0 < s1; v0 += 32) {
        int v = v0 + lane;
        float sv = (v < s1) ? row[v] : -1.0e8f;
        bool cand = (v < s1) && (sv != -1.0e8f);
        unsigned mk = __ballot_sync(0xffffffffu, cand);
        int rank = __popc(mk & ((1u << lane) - 1u));
        if (cand) {
            int p = (qt + rank) & 63;
            qv[warp][p] = (unsigned short)v;
            qs[warp][p] = sv;
        }
        qt += __popc(mk);
        while (qt - qh >= 32) {
            __syncwarp();
            int p = (qh + lane) & 63;
            int vv = qv[warp][p];
            float smv = qs[warp][p];
            __syncwarp();
            qh += 32;
            float cv = gproc(smv, vv, b, k1t, k2t, rb, best);
#pragma unroll
            for (int o = 16; o; o >>= 1)
                cv = fmaxf(cv, __shfl_xor_sync(0xffffffffu, cv, o));
            rb = fmaxf(rb, cv);
        }
    }
    {
        int rem = qt - qh;
        __syncwarp();
        if (lane < rem) {
            int p = (qh + lane) & 63;
            int vv = qv[warp][p];
            float smv = qs[warp][p];
            (void)gproc(smv, vv, b, k1t, k2t, rb, best);
        }
    }
#pragma unroll
    for (int o = 16; o; o >>= 1) {
        unsigned long long ob = __shfl_xor_sync(0xffffffffu, best, o);
        if (ob > best) best = ob;
    }
    if (lane == 0) wbest[warp] = best;
    __syncthreads();
    if (tid == 0) {
        unsigned long long bb = 0ULL;
#pragma unroll
        for (int w = 0; w < 8; ++w) bb = (wbest[w] > bb) ? wbest[w] : bb;
        int idx = (bb == 0ULL) ? 0 : (int)(~(unsigned)(bb & 0xFFFFFFFFu));
        if (idx < 0) idx = 0;
        if (idx >= VV) idx = VV - 1;
        sidx = idx;
        if (idx_out) idx_out[b * SS + t] = (float)idx;
    }
    __syncthreads();
    if (tid < OED) {
        float val = order_embedding[(size_t)sidx * OED + tid];
        unsigned hh, hl; split1(val, hh, hl);
        g_oe_hi[b * OED + tid] = hh;
        g_oe_lo[b * OED + tid] = hl;
    }
}

// ---------------- launch ----------------
extern "C" void kernel_launch(void* const* d_in, const int* in_sizes, int n_in,
                              void* d_out, int out_size) {
    const float*    enc        = (const float*)d_in[0];
    const int*      loc_idxs   = (const int*)d_in[2];
    const unsigned* ord_masks  = (const unsigned*)d_in[3];
    const float*    power_1h   = (const float*)d_in[4];
    const float*    order_emb  = (const float*)d_in[5];
    const float*    power_W    = (const float*)d_in[6];
    const float*    power_b    = (const float*)d_in[7];
    const float*    W_ih       = (const float*)d_in[8];
    const float*    W_hh       = (const float*)d_in[9];
    const float*    b_ih       = (const float*)d_in[10];
    const float*    b_hh       = (const float*)d_in[11];
    const float*    out_W      = (const float*)d_in[12];
    const float*    out_b      = (const float*)d_in[13];
    const float*    master     = (const float*)d_in[14];

    float* out = (float*)d_out;
    float* idx_out = nullptr;
    float* scores_out = nullptr;
    const long long NSC = (long long)BB * SS * VV;
    if ((long long)out_size == NSC + (long long)BB * SS) { idx_out = out; scores_out = out + BB * SS; }
    else if ((long long)out_size == NSC)                 { scores_out = out; }
    else if (out_size == BB * SS)                        { idx_out = out; }
    else { scores_out = out; }

    float* g_scores_ptr = nullptr;
    cudaGetSymbolAddress((void**)&g_scores_ptr, g_scores);
    float*    sc_base = scores_out ? scores_out : g_scores_ptr;
    long long pitch   = scores_out ? (long long)SS * VV : (long long)VV;

    cudaFuncSetAttribute(scores_mma_kernel,
                         cudaFuncAttributeMaxDynamicSharedMemorySize, SCORES_SMEM);

    precompute_kernel<<<BB, 256>>>(enc, loc_idxs, power_1h, power_W, power_b, master);
    pack_gw_kernel<<<(G4H * KPAD + 255) / 256, 256>>>(W_ih, W_hh, b_ih, b_hh);
    pack_ow_kernel<<<(VV * HD + 255) / 256, 256>>>(out_W);

    dim3 g1grid((G4H + 63) / 64, BB / 64);           // 13 x 8 = 104 blocks
    dim3 g3grid((VV + 127) / 128, BB / 128);         // 102 x 4 = 408 blocks
    for (int t = 0; t < SS; ++t) {
        long long off = scores_out ? (long long)t * VV : 0;
        gates_fused_kernel<<<g1grid, 256>>>(t);
        scores_mma_kernel<<<g3grid, 256, SCORES_SMEM>>>(out_b, ord_masks, sc_base, pitch, off, t);
        sample_kernel<<<BB, 256>>>(sc_base, pitch, off, order_emb, idx_out, t);
    }
}

// round 14
// speedup vs baseline: 1.2067x; 1.2012x over previous
#include <cuda_runtime.h>

#define BB   512
#define SS   17
#define LL   81
#define VV   13030
#define ENCD 240
#define OED  80
#define PED  60
#define IND  380     // ENC + OE + PE
#define HD   200
#define G4H  800     // 4*H
#define KPAD 592     // 37*16, padded K for gates GEMM (reordered [h|enc|oe|pe|0])

// ---------------- scratch (static device globals; no allocation) ----------------
__device__ __align__(16) unsigned g_gW_hi[G4H * KPAD];   // permuted+packed gate weights
__device__ __align__(16) unsigned g_gW_lo[G4H * KPAD];
__device__ __align__(16) float    g_gbias[G4H];
__device__ __align__(16) unsigned g_oW_hi[VV * HD];
__device__ __align__(16) unsigned g_oW_lo[VV * HD];
__device__ __align__(16) unsigned g_le_hi[SS * BB * ENCD];
__device__ __align__(16) unsigned g_le_lo[SS * BB * ENCD];
__device__ __align__(16) unsigned g_pe_hi[BB * PED];
__device__ __align__(16) unsigned g_pe_lo[BB * PED];
__device__ __align__(16) unsigned g_h_hi[BB * HD];
__device__ __align__(16) unsigned g_h_lo[BB * HD];
__device__ __align__(16) unsigned g_oe_hi[BB * OED];
__device__ __align__(16) unsigned g_oe_lo[BB * OED];
__device__ __align__(16) float    g_c[BB * HD];
__device__ int      g_invalid[BB];
__device__ unsigned g_keys[2 * SS];
__device__ __align__(16) float g_scores[BB * VV];        // scratch when no scores output

// ---------------- threefry2x32 (matches jax/_src/prng.py reference) ----------------
__device__ __forceinline__ uint2 tf2x32(unsigned k0, unsigned k1,
                                        unsigned x0, unsigned x1) {
    unsigned ks2 = k0 ^ k1 ^ 0x1BD11BDAu;
    x0 += k0; x1 += k1;
#define TFR(r) { x0 += x1; x1 = __funnelshift_l(x1, x1, (r)); x1 ^= x0; }
    TFR(13) TFR(15) TFR(26) TFR(6)
    x0 += k1; x1 += ks2 + 1u;
    TFR(17) TFR(29) TFR(16) TFR(24)
    x0 += ks2; x1 += k0 + 2u;
    TFR(13) TFR(15) TFR(26) TFR(6)
    x0 += k0; x1 += k1 + 3u;
    TFR(17) TFR(29) TFR(16) TFR(24)
    x0 += k1; x1 += ks2 + 4u;
    TFR(13) TFR(15) TFR(26) TFR(6)
    x0 += ks2; x1 += k0 + 5u;
#undef TFR
    return make_uint2(x0, x1);
}

// ---------------- accurate fp32 natural log (fdlibm e_logf; fast-math-proof) ----------------
__device__ __forceinline__ float alogf(float x) {
    int ib = __float_as_int(x);
    int k  = ((ib >> 23) & 0xFF) - 126;
    float m = __int_as_float((ib & 0x007FFFFF) | 0x3F000000);
    if (m < 0.70710678f) { m = m + m; k -= 1; }
    float f = m - 1.0f;
    float s = f / (2.0f + f);
    float z = s * s;
    float w = z * z;
    float t1 = w * (0.40000972152f + w * 0.24279078841f);
    float t2 = z * (0.66666662693f + w * 0.28498786688f);
    float R  = t2 + t1;
    float hfsq = 0.5f * f * f;
    float dk = (float)k;
    return dk * 0.69313812256f - ((hfsq - (s * (hfsq + R) + dk * 9.0580006145e-06f)) - f);
}

// ---------------- tf32 helpers ----------------
__device__ __forceinline__ unsigned f2tf32(float x) {
    unsigned r;
    asm("cvt.rna.tf32.f32 %0, %1;" : "=r"(r) : "f"(x));
    return r;
}
__device__ __forceinline__ void mma_tf32(float* c, const unsigned* a, const unsigned* b) {
    asm volatile(
        "mma.sync.aligned.m16n8k8.row.col.f32.tf32.tf32.f32 "
        "{%0,%1,%2,%3}, {%4,%5,%6,%7}, {%8,%9}, {%0,%1,%2,%3};\n"
        : "+f"(c[0]), "+f"(c[1]), "+f"(c[2]), "+f"(c[3])
        : "r"(a[0]), "r"(a[1]), "r"(a[2]), "r"(a[3]), "r"(b[0]), "r"(b[1]));
}
__device__ __forceinline__ void split1(float x, unsigned& hi, unsigned& lo) {
    hi = f2tf32(x);
    lo = f2tf32(x - __uint_as_float(hi));
}

// cp.async 16B with zero-fill predicate
__device__ __forceinline__ void cpa16(void* sdst, const void* gsrc, bool pred) {
    unsigned saddr = (unsigned)__cvta_generic_to_shared(sdst);
    int sz = pred ? 16 : 0;
    asm volatile("cp.async.cg.shared.global [%0], [%1], 16, %2;\n"
                 :: "r"(saddr), "l"(gsrc), "r"(sz));
}

// ---------------- pack kernels (run once per launch) ----------------
// gate weights: row u' = unit*4 + gate; orig row = gate*HD + unit; k-order [h|enc|oe|pe|0pad]
__global__ __launch_bounds__(256) void pack_gw_kernel(
    const float* __restrict__ W_ih, const float* __restrict__ W_hh,
    const float* __restrict__ b_ih, const float* __restrict__ b_hh) {
    int idx = blockIdx.x * blockDim.x + threadIdx.x;
    if (idx >= G4H * KPAD) return;
    int up = idx / KPAD, k = idx - up * KPAD;
    int orig = (up & 3) * HD + (up >> 2);
    float v = 0.f;
    if (k < HD)        v = W_hh[orig * HD + k];
    else if (k < 580)  v = W_ih[orig * IND + (k - HD)];
    unsigned hi, lo; split1(v, hi, lo);
    g_gW_hi[idx] = hi; g_gW_lo[idx] = lo;
    if (k == 0) g_gbias[up] = b_ih[orig] + b_hh[orig];
}

__global__ __launch_bounds__(256) void pack_ow_kernel(const float* __restrict__ out_W) {
    int idx = blockIdx.x * blockDim.x + threadIdx.x;
    if (idx >= VV * HD) return;
    unsigned hi, lo; split1(out_W[idx], hi, lo);
    g_oW_hi[idx] = hi; g_oW_lo[idx] = lo;
}

// ---------------- kernel A: precompute loc_enc(split)/power_emb(split)/state/keys ----------------
__global__ __launch_bounds__(256) void precompute_kernel(
    const float* __restrict__ enc, const int* __restrict__ loc_idxs,
    const float* __restrict__ power_1h, const float* __restrict__ power_W,
    const float* __restrict__ power_b, const float* __restrict__ master) {
    __shared__ float sM[LL * LL];
    __shared__ float sAl[SS][LL];
    __shared__ float sDen[SS];
    __shared__ int   sLoc[LL];
    int b = blockIdx.x;
    int tid = threadIdx.x;

    for (int i = tid; i < LL * LL; i += 256) sM[i] = master[i];
    if (tid < LL) sLoc[tid] = loc_idxs[b * LL + tid];
    for (int i = tid; i < HD; i += 256) {
        g_h_hi[b * HD + i] = 0u; g_h_lo[b * HD + i] = 0u; g_c[b * HD + i] = 0.f;
    }
    for (int i = tid; i < OED; i += 256) { g_oe_hi[b * OED + i] = 0u; g_oe_lo[b * OED + i] = 0u; }
    if (tid < PED) {
        float acc = power_b[tid];
        for (int j = 0; j < 7; ++j) acc += power_1h[b * 7 + j] * power_W[tid * 7 + j];
        unsigned hi, lo; split1(acc, hi, lo);
        g_pe_hi[b * PED + tid] = hi; g_pe_lo[b * PED + tid] = lo;
    }
    if (b == 0 && tid < SS) {
        uint2 r = tf2x32(0u, 42u, 0u, (unsigned)tid);
        g_keys[2 * tid]     = r.x;
        g_keys[2 * tid + 1] = r.y;
    }
    __syncthreads();

    if (tid == 0) {
        int any = 0;
        for (int l = 0; l < LL; ++l) any |= (sLoc[l] != -1);
        g_invalid[b] = !any;
    }
    for (int e = tid; e < SS * LL; e += 256) {
        int t = e / LL, j = e % LL;
        float a = 0.f;
        for (int l = 0; l < LL; ++l) {
            int li = sLoc[l];
            if (li == t || li == -2) a += sM[l * LL + j];
        }
        sAl[t][j] = a;
    }
    __syncthreads();
    if (tid < SS) {
        float d = 0.f;
        for (int j = 0; j < LL; ++j) d += sAl[tid][j];
        sDen[tid] = d;
    }
    __syncthreads();
    for (int e = tid; e < SS * LL; e += 256) {
        int t = e / LL, j = e % LL;
        float d = sDen[t];
        sAl[t][j] = (d != 0.f) ? sAl[t][j] / d : 0.f;
    }
    __syncthreads();
    if (tid < ENCD) {
        float acc[SS];
#pragma unroll
        for (int t = 0; t < SS; ++t) acc[t] = 0.f;
        for (int l = 0; l < LL; ++l) {
            float v = enc[((size_t)b * LL + l) * ENCD + tid];
#pragma unroll
            for (int t = 0; t < SS; ++t) acc[t] += sAl[t][l] * v;
        }
#pragma unroll
        for (int t = 0; t < SS; ++t) {
            unsigned hi, lo; split1(acc[t], hi, lo);
            size_t o = ((size_t)t * BB + b) * ENCD + tid;
            g_le_hi[o] = hi; g_le_lo[o] = lo;
        }
    }
}

// ---------------- G1: fused gates GEMM + LSTM update (64x64 tiles, cp.async pipeline) ----------------
// grid = (13, 8). Gate-interleaved rows: any 4-aligned 64-row window holds complete i,f,g,o quads.
struct GatesSM {
    union {
        struct {
            unsigned AH[2][64][20];
            unsigned AL[2][64][20];
            unsigned BH[2][64][20];
            unsigned BL[2][64][20];
        } p;
        float C[64][68];
    };
};

__global__ __launch_bounds__(256) void gates_fused_kernel(int t) {
    __shared__ GatesSM u;
    __shared__ float sBias[64];
    int tid = threadIdx.x;
    int u0 = blockIdx.x * 64, b0 = blockIdx.y * 64;
    int lane = tid & 31, warp = tid >> 5;
    int wv = warp & 1, wb = warp >> 1;         // 2 (rows) x 4 (cols)
    int g = lane >> 2, tig = lane & 3;

    if (tid < 64) {
        int up = u0 + tid;
        sBias[tid] = (up < G4H) ? g_gbias[up] : 0.f;
    }

    float acc[2][2][4];
#pragma unroll
    for (int mt = 0; mt < 2; ++mt)
#pragma unroll
        for (int nt = 0; nt < 2; ++nt)
#pragma unroll
            for (int q = 0; q < 4; ++q) acc[mt][nt][q] = 0.f;

    int arow = tid >> 2, akp = (tid & 3) * 4;  // 64 rows x 16k, 1 cpa16 per plane per thread
    int brow = arow,    bkp = akp;
    int up = u0 + arow;
    bool pA = (up < G4H);
    size_t abase = (size_t)(pA ? up : 0) * KPAD;
    int bb = b0 + brow;
    const size_t le_row = (size_t)t * BB * ENCD + (size_t)bb * ENCD;

    const int NIT = KPAD / 16;                 // 37
    auto issue = [&](int it, int bi) {
        int k0 = it * 16;
        // A: packed gate weights
        cpa16(&u.p.AH[bi][arow][akp], g_gW_hi + abase + k0 + akp, pA);
        cpa16(&u.p.AL[bi][arow][akp], g_gW_lo + abase + k0 + akp, pA);
        // B: x row, k-order [h|le|oe|pe|0]
        int k = k0 + bkp;
        const unsigned *sh = g_h_hi, *sl = g_h_lo;
        bool pB = true;
        if (k < HD)                   { sh = g_h_hi + bb * HD + k;            sl = g_h_lo + bb * HD + k; }
        else if (k < HD + ENCD)       { sh = g_le_hi + le_row + (k - HD);     sl = g_le_lo + le_row + (k - HD); }
        else if (k < HD + ENCD + OED) { sh = g_oe_hi + bb * OED + (k - 440);  sl = g_oe_lo + bb * OED + (k - 440); }
        else if (k < 580)             { sh = g_pe_hi + bb * PED + (k - 520);  sl = g_pe_lo + bb * PED + (k - 520); }
        else                          { pB = false; }
        cpa16(&u.p.BH[bi][brow][bkp], sh, pB);
        cpa16(&u.p.BL[bi][brow][bkp], sl, pB);
    };

    issue(0, 0);
    asm volatile("cp.async.commit_group;");
    for (int it = 0; it < NIT; ++it) {
        if (it + 1 < NIT) issue(it + 1, (it + 1) & 1);
        asm volatile("cp.async.commit_group;");
        asm volatile("cp.async.wait_group 1;");
        __syncthreads();
        int bi = it & 1;
#pragma unroll
        for (int kk = 0; kk < 16; kk += 8) {
            unsigned afh[2][4], afl[2][4], bfh[2][2], bfl[2][2];
#pragma unroll
            for (int mt = 0; mt < 2; ++mt) {
                int r = wv * 32 + mt * 16 + g;
                afh[mt][0] = u.p.AH[bi][r][kk + tig];
                afh[mt][1] = u.p.AH[bi][r + 8][kk + tig];
                afh[mt][2] = u.p.AH[bi][r][kk + tig + 4];
                afh[mt][3] = u.p.AH[bi][r + 8][kk + tig + 4];
                afl[mt][0] = u.p.AL[bi][r][kk + tig];
                afl[mt][1] = u.p.AL[bi][r + 8][kk + tig];
                afl[mt][2] = u.p.AL[bi][r][kk + tig + 4];
                afl[mt][3] = u.p.AL[bi][r + 8][kk + tig + 4];
            }
#pragma unroll
            for (int nt = 0; nt < 2; ++nt) {
                int c = wb * 16 + nt * 8 + g;
                bfh[nt][0] = u.p.BH[bi][c][kk + tig];
                bfh[nt][1] = u.p.BH[bi][c][kk + tig + 4];
                bfl[nt][0] = u.p.BL[bi][c][kk + tig];
                bfl[nt][1] = u.p.BL[bi][c][kk + tig + 4];
            }
#pragma unroll
            for (int mt = 0; mt < 2; ++mt)
#pragma unroll
                for (int nt = 0; nt < 2; ++nt) {
                    mma_tf32(acc[mt][nt], afh[mt], bfl[nt]);
                    mma_tf32(acc[mt][nt], afl[mt], bfh[nt]);
                    mma_tf32(acc[mt][nt], afh[mt], bfh[nt]);
                }
        }
        __syncthreads();
    }

    // transpose accumulators into C[b][u'-local]
#pragma unroll
    for (int nt = 0; nt < 2; ++nt)
#pragma unroll
        for (int cc = 0; cc < 2; ++cc) {
            int bl = wb * 16 + nt * 8 + 2 * tig + cc;
#pragma unroll
            for (int mt = 0; mt < 2; ++mt)
#pragma unroll
                for (int rr = 0; rr < 2; ++rr) {
                    int vl = wv * 32 + mt * 16 + g + rr * 8;
                    u.C[bl][vl] = acc[mt][nt][rr * 2 + cc];
                }
        }
    __syncthreads();

    // fused LSTM pointwise update: one (b, unit) per work item
    int base = u0 >> 2;                         // first unit in this tile
    int nU = (G4H - u0 >= 64) ? 16 : ((G4H - u0) >> 2);
    int total = 64 * nU;
    for (int e = tid; e < total; e += 256) {
        int bl, un;
        if (nU == 16) { bl = e >> 4; un = e & 15; }
        else          { bl = e / nU; un = e - bl * nU; }
        float gi = u.C[bl][un * 4 + 0] + sBias[un * 4 + 0];
        float gf = u.C[bl][un * 4 + 1] + sBias[un * 4 + 1];
        float gg = u.C[bl][un * 4 + 2] + sBias[un * 4 + 2];
        float go = u.C[bl][un * 4 + 3] + sBias[un * 4 + 3];
        int b = b0 + bl, unit = base + un;
        float cprev = g_c[b * HD + unit];
        float si = 1.f / (1.f + expf(-gi));
        float sf = 1.f / (1.f + expf(-gf));
        float so = 1.f / (1.f + expf(-go));
        float c = sf * cprev + si * tanhf(gg);
        float h = so * tanhf(c);
        g_c[b * HD + unit] = c;
        unsigned hh, hl; split1(h, hh, hl);
        g_h_hi[b * HD + unit] = hh;
        g_h_lo[b * HD + unit] = hl;
    }
}

// ---------------- G3: scores GEMM, 128v x 64b block, 32x32 warp tiles, cp.async pipeline ----------------
struct ScoresSM {
    unsigned AH[2][128][20];   // 20480 B
    unsigned AL[2][128][20];
    unsigned BH[2][64][20];    // 10240 B
    unsigned BL[2][64][20];
};  // 61440 bytes

#define SCORES_SMEM (61440 + 512)

__global__ __launch_bounds__(256) void scores_mma_kernel(
    const float* __restrict__ out_b, const unsigned* __restrict__ order_masks,
    float* __restrict__ sc_base, long long pitch, long long off, int t) {
    extern __shared__ __align__(16) unsigned char dsm[];
    ScoresSM* sm = (ScoresSM*)dsm;
    float (*C)[132] = (float(*)[132])dsm;               // aliases buffers after k-loop
    float* sOutB = (float*)(dsm + sizeof(ScoresSM));
    int tid = threadIdx.x;
    int v0 = blockIdx.x * 128, b0 = blockIdx.y * 64;
    int lane = tid & 31, warp = tid >> 5;
    int wv = warp & 3, wb = warp >> 2;                  // 4 v-quarters x 2 b-halves
    int g = lane >> 2, tig = lane & 3;

    if (tid < 128) {
        int v = v0 + tid;
        sOutB[tid] = (v < VV) ? out_b[v] : 0.f;
    }

    float acc[2][4][4];
#pragma unroll
    for (int mt = 0; mt < 2; ++mt)
#pragma unroll
        for (int nt = 0; nt < 4; ++nt)
#pragma unroll
            for (int q = 0; q < 4; ++q) acc[mt][nt][q] = 0.f;

    int arow = tid >> 1, akq = (tid & 1) * 8;   // A: 2 threads/row, 4 cpa16 each
    int brow = tid >> 2, bkq = (tid & 3) * 4;   // B: 4 threads/row, 2 cpa16 each
    int va = v0 + arow;
    size_t aoff = (va < VV) ? (size_t)va * HD : 0;
    int bb = b0 + brow;

    const int NIT = 13;                                  // 13*16 = 208 >= HD
    auto issue = [&](int it, int bi) {
        int k0 = it * 16;
        int kA0 = k0 + akq, kA1 = k0 + akq + 4, kB = k0 + bkq;
        bool pA0 = (va < VV) && (kA0 < HD);
        bool pA1 = (va < VV) && (kA1 < HD);
        bool pB  = (kB < HD);
        int cA0 = pA0 ? kA0 : 0, cA1 = pA1 ? kA1 : 0, cB = pB ? kB : 0;
        cpa16(&sm->AH[bi][arow][akq],     g_oW_hi + aoff + cA0, pA0);
        cpa16(&sm->AH[bi][arow][akq + 4], g_oW_hi + aoff + cA1, pA1);
        cpa16(&sm->AL[bi][arow][akq],     g_oW_lo + aoff + cA0, pA0);
        cpa16(&sm->AL[bi][arow][akq + 4], g_oW_lo + aoff + cA1, pA1);
        cpa16(&sm->BH[bi][brow][bkq],     g_h_hi + bb * HD + cB, pB);
        cpa16(&sm->BL[bi][brow][bkq],     g_h_lo + bb * HD + cB, pB);
    };

    issue(0, 0);
    asm volatile("cp.async.commit_group;");
    for (int it = 0; it < NIT; ++it) {
        if (it + 1 < NIT) issue(it + 1, (it + 1) & 1);
        asm volatile("cp.async.commit_group;");
        asm volatile("cp.async.wait_group 1;");
        __syncthreads();
        int bi = it & 1;
#pragma unroll
        for (int kk = 0; kk < 16; kk += 8) {
            unsigned afh[2][4], afl[2][4], bfh[4][2], bfl[4][2];
#pragma unroll
            for (int mt = 0; mt < 2; ++mt) {
                int r = wv * 32 + mt * 16 + g;
                afh[mt][0] = sm->AH[bi][r][kk + tig];
                afh[mt][1] = sm->AH[bi][r + 8][kk + tig];
                afh[mt][2] = sm->AH[bi][r][kk + tig + 4];
                afh[mt][3] = sm->AH[bi][r + 8][kk + tig + 4];
                afl[mt][0] = sm->AL[bi][r][kk + tig];
                afl[mt][1] = sm->AL[bi][r + 8][kk + tig];
                afl[mt][2] = sm->AL[bi][r][kk + tig + 4];
                afl[mt][3] = sm->AL[bi][r + 8][kk + tig + 4];
            }
#pragma unroll
            for (int nt = 0; nt < 4; ++nt) {
                int c = wb * 32 + nt * 8 + g;
                bfh[nt][0] = sm->BH[bi][c][kk + tig];
                bfh[nt][1] = sm->BH[bi][c][kk + tig + 4];
                bfl[nt][0] = sm->BL[bi][c][kk + tig];
                bfl[nt][1] = sm->BL[bi][c][kk + tig + 4];
            }
#pragma unroll
            for (int mt = 0; mt < 2; ++mt)
#pragma unroll
                for (int nt = 0; nt < 4; ++nt) {
                    mma_tf32(acc[mt][nt], afh[mt], bfl[nt]);
                    mma_tf32(acc[mt][nt], afl[mt], bfh[nt]);
                    mma_tf32(acc[mt][nt], afh[mt], bfh[nt]);
                }
        }
        __syncthreads();
    }

    // transpose accumulators through smem (aliases the now-idle buffers)
#pragma unroll
    for (int nt = 0; nt < 4; ++nt)
#pragma unroll
        for (int cc = 0; cc < 2; ++cc) {
            int bl = wb * 32 + nt * 8 + 2 * tig + cc;
#pragma unroll
            for (int mt = 0; mt < 2; ++mt)
#pragma unroll
                for (int rr = 0; rr < 2; ++rr) {
                    int vl = wv * 32 + mt * 16 + g + rr * 8;
                    C[bl][vl] = acc[mt][nt][rr * 2 + cc];
                }
        }
    __syncthreads();

    // coalesced float2 store with bias + mask
    for (int e = tid; e < 64 * 64; e += 256) {
        int bl = e >> 6, v2 = e & 63;
        int b = b0 + bl;
        int v = v0 + v2 * 2;
        if (v >= VV) continue;
        float2 c = *(float2*)&C[bl][v2 * 2];
        c.x += sOutB[v2 * 2];
        c.y += sOutB[v2 * 2 + 1];
        int inv = g_invalid[b];
        uint2 m2 = *(const uint2*)(order_masks + ((size_t)b * SS + t) * VV + v);
        bool ma = inv || (m2.x != 0u);
        bool mb = inv || (m2.y != 0u);
        float2 r;
        r.x = fminf(c.x, ma ? 9.0e8f : -1.0e8f);
        r.y = fminf(c.y, mb ? 9.0e8f : -1.0e8f);
        *(float2*)(sc_base + (long long)b * pitch + off + v) = r;
    }
}

// ---------------- G4: sample kernel — ballot-compacted gumbel argmax + finish ----------------
__device__ __forceinline__ float gproc(float sm, int vv, int b,
                                       unsigned k1t, unsigned k2t,
                                       float rb, unsigned long long& best) {
    uint2 r = tf2x32(k1t, k2t, 0u, (unsigned)(b * VV + vv));
    unsigned bits = r.x ^ r.y;
    float uf = __uint_as_float((bits >> 9) | 0x3F800000u) - 1.0f;
    uf = fmaxf(uf + 1.17549435e-38f, 1.17549435e-38f);
    float lnu_lo = fmaf((float)__float_as_int(uf), 8.2629582e-8f, -88.029694f);
    float e_min = -lnu_lo - 0.0605f;
    float gub = 3.0e38f;
    if (e_min > 1.17549435e-38f) {
        float lne_lo = fmaf((float)__float_as_int(e_min), 8.2629582e-8f, -88.029694f);
        gub = -lne_lo + 1.0e-3f;
    }
    if (sm + gub < rb) return -3.0e38f;
    float gum = -alogf(-alogf(uf));
    float cv = sm + gum;
    unsigned ub = __float_as_uint(cv);
    ub = (ub & 0x80000000u) ? ~ub : (ub | 0x80000000u);
    unsigned long long packed = ((unsigned long long)ub << 32) | (unsigned)(~(unsigned)vv);
    if (packed > best) best = packed;
    return cv;
}

__global__ __launch_bounds__(256) void sample_kernel(
    const float* __restrict__ sc_base, long long pitch, long long off,
    const float* __restrict__ order_embedding, float* __restrict__ idx_out, int t) {
    int b = blockIdx.x;
    const float* row = sc_base + (long long)b * pitch + off;
    int tid = threadIdx.x, warp = tid >> 5, lane = tid & 31;
    __shared__ unsigned short qv[8][64];
    __shared__ float qs[8][64];
    __shared__ unsigned long long wbest[8];
    __shared__ int sidx;
    unsigned k1t = g_keys[2 * t], k2t = g_keys[2 * t + 1];
    const int SEG = 1632;
    int s0 = warp * SEG;
    int s1 = min(s0 + SEG, VV);
    unsigned long long best = 0ULL;
    float rb = -3.0e38f;
    int qh = 0, qt = 0;

    for (int v0 = s0; v0 < s1; v0 += 32) {
        int v = v0 + lane;
        float sv = (v < s1) ? row[v] : -1.0e8f;
        bool cand = (v < s1) && (sv != -1.0e8f);
        unsigned mk = __ballot_sync(0xffffffffu, cand);
        int rank = __popc(mk & ((1u << lane) - 1u));
        if (cand) {
            int p = (qt + rank) & 63;
            qv[warp][p] = (unsigned short)v;
            qs[warp][p] = sv;
        }
        qt += __popc(mk);
        while (qt - qh >= 32) {
            __syncwarp();
            int p = (qh + lane) & 63;
            int vv = qv[warp][p];
            float smv = qs[warp][p];
            __syncwarp();
            qh += 32;
            float cv = gproc(smv, vv, b, k1t, k2t, rb, best);
#pragma unroll
            for (int o = 16; o; o >>= 1)
                cv = fmaxf(cv, __shfl_xor_sync(0xffffffffu, cv, o));
            rb = fmaxf(rb, cv);
        }
    }
    {
        int rem = qt - qh;
        __syncwarp();
        if (lane < rem) {
            int p = (qh + lane) & 63;
            int vv = qv[warp][p];
            float smv = qs[warp][p];
            (void)gproc(smv, vv, b, k1t, k2t, rb, best);
        }
    }
#pragma unroll
    for (int o = 16; o; o >>= 1) {
        unsigned long long ob = __shfl_xor_sync(0xffffffffu, best, o);
        if (ob > best) best = ob;
    }
    if (lane == 0) wbest[warp] = best;
    __syncthreads();
    if (tid == 0) {
        unsigned long long bb = 0ULL;
#pragma unroll
        for (int w = 0; w < 8; ++w) bb = (wbest[w] > bb) ? wbest[w] : bb;
        int idx = (bb == 0ULL) ? 0 : (int)(~(unsigned)(bb & 0xFFFFFFFFu));
        if (idx < 0) idx = 0;
        if (idx >= VV) idx = VV - 1;
        sidx = idx;
        if (idx_out) idx_out[b * SS + t] = (float)idx;
    }
    __syncthreads();
    if (tid < OED) {
        float val = order_embedding[(size_t)sidx * OED + tid];
        unsigned hh, hl; split1(val, hh, hl);
        g_oe_hi[b * OED + tid] = hh;
        g_oe_lo[b * OED + tid] = hl;
    }
}

// ---------------- launch ----------------
extern "C" void kernel_launch(void* const* d_in, const int* in_sizes, int n_in,
                              void* d_out, int out_size) {
    const float*    enc        = (const float*)d_in[0];
    const int*      loc_idxs   = (const int*)d_in[2];
    const unsigned* ord_masks  = (const unsigned*)d_in[3];
    const float*    power_1h   = (const float*)d_in[4];
    const float*    order_emb  = (const float*)d_in[5];
    const float*    power_W    = (const float*)d_in[6];
    const float*    power_b    = (const float*)d_in[7];
    const float*    W_ih       = (const float*)d_in[8];
    const float*    W_hh       = (const float*)d_in[9];
    const float*    b_ih       = (const float*)d_in[10];
    const float*    b_hh       = (const float*)d_in[11];
    const float*    out_W      = (const float*)d_in[12];
    const float*    out_b      = (const float*)d_in[13];
    const float*    master     = (const float*)d_in[14];

    float* out = (float*)d_out;
    float* idx_out = nullptr;
    float* scores_out = nullptr;
    const long long NSC = (long long)BB * SS * VV;
    if ((long long)out_size == NSC + (long long)BB * SS) { idx_out = out; scores_out = out + BB * SS; }
    else if ((long long)out_size == NSC)                 { scores_out = out; }
    else if (out_size == BB * SS)                        { idx_out = out; }
    else { scores_out = out; }

    float* g_scores_ptr = nullptr;
    cudaGetSymbolAddress((void**)&g_scores_ptr, g_scores);
    float*    sc_base = scores_out ? scores_out : g_scores_ptr;
    long long pitch   = scores_out ? (long long)SS * VV : (long long)VV;

    cudaFuncSetAttribute(scores_mma_kernel,
                         cudaFuncAttributeMaxDynamicSharedMemorySize, SCORES_SMEM);

    precompute_kernel<<<BB, 256>>>(enc, loc_idxs, power_1h, power_W, power_b, master);
    pack_gw_kernel<<<(G4H * KPAD + 255) / 256, 256>>>(W_ih, W_hh, b_ih, b_hh);
    pack_ow_kernel<<<(VV * HD + 255) / 256, 256>>>(out_W);

    dim3 g1grid((G4H + 63) / 64, BB / 64);           // 13 x 8 = 104 blocks
    dim3 g3grid((VV + 127) / 128, BB / 64);          // 102 x 8 = 816 blocks
    for (int t = 0; t < SS; ++t) {
        long long off = scores_out ? (long long)t * VV : 0;
        gates_fused_kernel<<<g1grid, 256>>>(t);
        scores_mma_kernel<<<g3grid, 256, SCORES_SMEM>>>(out_b, ord_masks, sc_base, pitch, off, t);
        sample_kernel<<<BB, 256>>>(sc_base, pitch, off, order_emb, idx_out, t);
    }
}

// round 15
// speedup vs baseline: 1.2139x; 1.0060x over previous
#include <cuda_runtime.h>

#define BB   512
#define SS   17
#define LL   81
#define VV   13030
#define ENCD 240
#define OED  80
#define PED  60
#define IND  380     // ENC + OE + PE
#define HD   200
#define G4H  800     // 4*H
#define KPAD 592     // 37*16, padded K for gates GEMM (reordered [h|enc|oe|pe|0])

// ---------------- scratch (static device globals; no allocation) ----------------
__device__ __align__(16) unsigned g_gW_hi[G4H * KPAD];   // permuted+packed gate weights
__device__ __align__(16) unsigned g_gW_lo[G4H * KPAD];
__device__ __align__(16) float    g_gbias[G4H];
__device__ __align__(16) unsigned g_oW_hi[VV * HD];
__device__ __align__(16) unsigned g_oW_lo[VV * HD];
__device__ __align__(16) unsigned g_le_hi[SS * BB * ENCD];
__device__ __align__(16) unsigned g_le_lo[SS * BB * ENCD];
__device__ __align__(16) unsigned g_pe_hi[BB * PED];
__device__ __align__(16) unsigned g_pe_lo[BB * PED];
__device__ __align__(16) unsigned g_h_hi[BB * HD];
__device__ __align__(16) unsigned g_h_lo[BB * HD];
__device__ __align__(16) unsigned g_oe_hi[BB * OED];
__device__ __align__(16) unsigned g_oe_lo[BB * OED];
__device__ __align__(16) float    g_c[BB * HD];
__device__ int      g_invalid[BB];
__device__ unsigned g_keys[2 * SS];
__device__ __align__(16) float g_scores[BB * VV];        // scratch when no scores output

// ---------------- threefry2x32 (matches jax/_src/prng.py reference) ----------------
__device__ __forceinline__ uint2 tf2x32(unsigned k0, unsigned k1,
                                        unsigned x0, unsigned x1) {
    unsigned ks2 = k0 ^ k1 ^ 0x1BD11BDAu;
    x0 += k0; x1 += k1;
#define TFR(r) { x0 += x1; x1 = __funnelshift_l(x1, x1, (r)); x1 ^= x0; }
    TFR(13) TFR(15) TFR(26) TFR(6)
    x0 += k1; x1 += ks2 + 1u;
    TFR(17) TFR(29) TFR(16) TFR(24)
    x0 += ks2; x1 += k0 + 2u;
    TFR(13) TFR(15) TFR(26) TFR(6)
    x0 += k0; x1 += k1 + 3u;
    TFR(17) TFR(29) TFR(16) TFR(24)
    x0 += k1; x1 += ks2 + 4u;
    TFR(13) TFR(15) TFR(26) TFR(6)
    x0 += ks2; x1 += k0 + 5u;
#undef TFR
    return make_uint2(x0, x1);
}

// ---------------- accurate fp32 natural log (fdlibm e_logf; fast-math-proof) ----------------
__device__ __forceinline__ float alogf(float x) {
    int ib = __float_as_int(x);
    int k  = ((ib >> 23) & 0xFF) - 126;
    float m = __int_as_float((ib & 0x007FFFFF) | 0x3F000000);
    if (m < 0.70710678f) { m = m + m; k -= 1; }
    float f = m - 1.0f;
    float s = f / (2.0f + f);
    float z = s * s;
    float w = z * z;
    float t1 = w * (0.40000972152f + w * 0.24279078841f);
    float t2 = z * (0.66666662693f + w * 0.28498786688f);
    float R  = t2 + t1;
    float hfsq = 0.5f * f * f;
    float dk = (float)k;
    return dk * 0.69313812256f - ((hfsq - (s * (hfsq + R) + dk * 9.0580006145e-06f)) - f);
}

// ---------------- tf32 helpers ----------------
__device__ __forceinline__ unsigned f2tf32(float x) {
    unsigned r;
    asm("cvt.rna.tf32.f32 %0, %1;" : "=r"(r) : "f"(x));
    return r;
}
__device__ __forceinline__ void mma_tf32(float* c, const unsigned* a, const unsigned* b) {
    asm volatile(
        "mma.sync.aligned.m16n8k8.row.col.f32.tf32.tf32.f32 "
        "{%0,%1,%2,%3}, {%4,%5,%6,%7}, {%8,%9}, {%0,%1,%2,%3};\n"
        : "+f"(c[0]), "+f"(c[1]), "+f"(c[2]), "+f"(c[3])
        : "r"(a[0]), "r"(a[1]), "r"(a[2]), "r"(a[3]), "r"(b[0]), "r"(b[1]));
}
__device__ __forceinline__ void split1(float x, unsigned& hi, unsigned& lo) {
    hi = f2tf32(x);
    lo = f2tf32(x - __uint_as_float(hi));
}

// cp.async 16B with zero-fill predicate
__device__ __forceinline__ void cpa16(void* sdst, const void* gsrc, bool pred) {
    unsigned saddr = (unsigned)__cvta_generic_to_shared(sdst);
    int sz = pred ? 16 : 0;
    asm volatile("cp.async.cg.shared.global [%0], [%1], 16, %2;\n"
                 :: "r"(saddr), "l"(gsrc), "r"(sz));
}

// ---------------- pack kernels (run once per launch) ----------------
// gate weights: row u' = unit*4 + gate; orig row = gate*HD + unit; k-order [h|enc|oe|pe|0pad]
__global__ __launch_bounds__(256) void pack_gw_kernel(
    const float* __restrict__ W_ih, const float* __restrict__ W_hh,
    const float* __restrict__ b_ih, const float* __restrict__ b_hh) {
    int idx = blockIdx.x * blockDim.x + threadIdx.x;
    if (idx >= G4H * KPAD) return;
    int up = idx / KPAD, k = idx - up * KPAD;
    int orig = (up & 3) * HD + (up >> 2);
    float v = 0.f;
    if (k < HD)        v = W_hh[orig * HD + k];
    else if (k < 580)  v = W_ih[orig * IND + (k - HD)];
    unsigned hi, lo; split1(v, hi, lo);
    g_gW_hi[idx] = hi; g_gW_lo[idx] = lo;
    if (k == 0) g_gbias[up] = b_ih[orig] + b_hh[orig];
}

__global__ __launch_bounds__(256) void pack_ow_kernel(const float* __restrict__ out_W) {
    int idx = blockIdx.x * blockDim.x + threadIdx.x;
    if (idx >= VV * HD) return;
    unsigned hi, lo; split1(out_W[idx], hi, lo);
    g_oW_hi[idx] = hi; g_oW_lo[idx] = lo;
}

// ---------------- kernel A: precompute loc_enc(split)/power_emb(split)/state/keys ----------------
__global__ __launch_bounds__(256) void precompute_kernel(
    const float* __restrict__ enc, const int* __restrict__ loc_idxs,
    const float* __restrict__ power_1h, const float* __restrict__ power_W,
    const float* __restrict__ power_b, const float* __restrict__ master) {
    __shared__ float sM[LL * LL];
    __shared__ float sAl[SS][LL];
    __shared__ float sDen[SS];
    __shared__ int   sLoc[LL];
    int b = blockIdx.x;
    int tid = threadIdx.x;

    for (int i = tid; i < LL * LL; i += 256) sM[i] = master[i];
    if (tid < LL) sLoc[tid] = loc_idxs[b * LL + tid];
    for (int i = tid; i < HD; i += 256) {
        g_h_hi[b * HD + i] = 0u; g_h_lo[b * HD + i] = 0u; g_c[b * HD + i] = 0.f;
    }
    for (int i = tid; i < OED; i += 256) { g_oe_hi[b * OED + i] = 0u; g_oe_lo[b * OED + i] = 0u; }
    if (tid < PED) {
        float acc = power_b[tid];
        for (int j = 0; j < 7; ++j) acc += power_1h[b * 7 + j] * power_W[tid * 7 + j];
        unsigned hi, lo; split1(acc, hi, lo);
        g_pe_hi[b * PED + tid] = hi; g_pe_lo[b * PED + tid] = lo;
    }
    if (b == 0 && tid < SS) {
        uint2 r = tf2x32(0u, 42u, 0u, (unsigned)tid);
        g_keys[2 * tid]     = r.x;
        g_keys[2 * tid + 1] = r.y;
    }
    __syncthreads();

    if (tid == 0) {
        int any = 0;
        for (int l = 0; l < LL; ++l) any |= (sLoc[l] != -1);
        g_invalid[b] = !any;
    }
    for (int e = tid; e < SS * LL; e += 256) {
        int t = e / LL, j = e % LL;
        float a = 0.f;
        for (int l = 0; l < LL; ++l) {
            int li = sLoc[l];
            if (li == t || li == -2) a += sM[l * LL + j];
        }
        sAl[t][j] = a;
    }
    __syncthreads();
    if (tid < SS) {
        float d = 0.f;
        for (int j = 0; j < LL; ++j) d += sAl[tid][j];
        sDen[tid] = d;
    }
    __syncthreads();
    for (int e = tid; e < SS * LL; e += 256) {
        int t = e / LL, j = e % LL;
        float d = sDen[t];
        sAl[t][j] = (d != 0.f) ? sAl[t][j] / d : 0.f;
    }
    __syncthreads();
    if (tid < ENCD) {
        float acc[SS];
#pragma unroll
        for (int t = 0; t < SS; ++t) acc[t] = 0.f;
        for (int l = 0; l < LL; ++l) {
            float v = enc[((size_t)b * LL + l) * ENCD + tid];
#pragma unroll
            for (int t = 0; t < SS; ++t) acc[t] += sAl[t][l] * v;
        }
#pragma unroll
        for (int t = 0; t < SS; ++t) {
            unsigned hi, lo; split1(acc[t], hi, lo);
            size_t o = ((size_t)t * BB + b) * ENCD + tid;
            g_le_hi[o] = hi; g_le_lo[o] = lo;
        }
    }
}

// ---------------- G1: fused gates GEMM + LSTM update (64x64 tiles, 3-stage cp.async pipeline) ----------------
// grid = (13, 8). Gate-interleaved rows: any 4-aligned 64-row window holds complete i,f,g,o quads.
struct GatesSM {
    union {
        struct {
            unsigned AH[3][64][20];
            unsigned AL[3][64][20];
            unsigned BH[3][64][20];
            unsigned BL[3][64][20];
        } p;
        float C[64][68];
    };
};

__global__ __launch_bounds__(256) void gates_fused_kernel(int t) {
    __shared__ GatesSM u;
    __shared__ float sBias[64];
    int tid = threadIdx.x;
    int u0 = blockIdx.x * 64, b0 = blockIdx.y * 64;
    int lane = tid & 31, warp = tid >> 5;
    int wv = warp & 1, wb = warp >> 1;         // 2 (rows) x 4 (cols)
    int g = lane >> 2, tig = lane & 3;

    if (tid < 64) {
        int up = u0 + tid;
        sBias[tid] = (up < G4H) ? g_gbias[up] : 0.f;
    }

    float acc[2][2][4];
#pragma unroll
    for (int mt = 0; mt < 2; ++mt)
#pragma unroll
        for (int nt = 0; nt < 2; ++nt)
#pragma unroll
            for (int q = 0; q < 4; ++q) acc[mt][nt][q] = 0.f;

    int arow = tid >> 2, akp = (tid & 3) * 4;  // 64 rows x 16k, 1 cpa16 per plane per thread
    int brow = arow,    bkp = akp;
    int up = u0 + arow;
    bool pA = (up < G4H);
    size_t abase = (size_t)(pA ? up : 0) * KPAD;
    int bb = b0 + brow;
    const size_t le_row = (size_t)t * BB * ENCD + (size_t)bb * ENCD;

    const int NIT = KPAD / 16;                 // 37
    auto issue = [&](int it, int bi) {
        int k0 = it * 16;
        // A: packed gate weights
        cpa16(&u.p.AH[bi][arow][akp], g_gW_hi + abase + k0 + akp, pA);
        cpa16(&u.p.AL[bi][arow][akp], g_gW_lo + abase + k0 + akp, pA);
        // B: x row, k-order [h|le|oe|pe|0]
        int k = k0 + bkp;
        const unsigned *sh = g_h_hi, *sl = g_h_lo;
        bool pB = true;
        if (k < HD)                   { sh = g_h_hi + bb * HD + k;            sl = g_h_lo + bb * HD + k; }
        else if (k < HD + ENCD)       { sh = g_le_hi + le_row + (k - HD);     sl = g_le_lo + le_row + (k - HD); }
        else if (k < HD + ENCD + OED) { sh = g_oe_hi + bb * OED + (k - 440);  sl = g_oe_lo + bb * OED + (k - 440); }
        else if (k < 580)             { sh = g_pe_hi + bb * PED + (k - 520);  sl = g_pe_lo + bb * PED + (k - 520); }
        else                          { pB = false; }
        cpa16(&u.p.BH[bi][brow][bkp], sh, pB);
        cpa16(&u.p.BL[bi][brow][bkp], sl, pB);
    };

    // 3-stage pipeline: two tiles always in flight
    issue(0, 0);
    asm volatile("cp.async.commit_group;");
    issue(1, 1);
    asm volatile("cp.async.commit_group;");
    for (int it = 0; it < NIT; ++it) {
        if (it + 2 < NIT) {
            issue(it + 2, (it + 2) % 3);
            asm volatile("cp.async.commit_group;");
            asm volatile("cp.async.wait_group 2;");
        } else {
            asm volatile("cp.async.wait_group 0;");
        }
        __syncthreads();
        int bi = it % 3;
#pragma unroll
        for (int kk = 0; kk < 16; kk += 8) {
            unsigned afh[2][4], afl[2][4], bfh[2][2], bfl[2][2];
#pragma unroll
            for (int mt = 0; mt < 2; ++mt) {
                int r = wv * 32 + mt * 16 + g;
                afh[mt][0] = u.p.AH[bi][r][kk + tig];
                afh[mt][1] = u.p.AH[bi][r + 8][kk + tig];
                afh[mt][2] = u.p.AH[bi][r][kk + tig + 4];
                afh[mt][3] = u.p.AH[bi][r + 8][kk + tig + 4];
                afl[mt][0] = u.p.AL[bi][r][kk + tig];
                afl[mt][1] = u.p.AL[bi][r + 8][kk + tig];
                afl[mt][2] = u.p.AL[bi][r][kk + tig + 4];
                afl[mt][3] = u.p.AL[bi][r + 8][kk + tig + 4];
            }
#pragma unroll
            for (int nt = 0; nt < 2; ++nt) {
                int c = wb * 16 + nt * 8 + g;
                bfh[nt][0] = u.p.BH[bi][c][kk + tig];
                bfh[nt][1] = u.p.BH[bi][c][kk + tig + 4];
                bfl[nt][0] = u.p.BL[bi][c][kk + tig];
                bfl[nt][1] = u.p.BL[bi][c][kk + tig + 4];
            }
#pragma unroll
            for (int mt = 0; mt < 2; ++mt)
#pragma unroll
                for (int nt = 0; nt < 2; ++nt) {
                    mma_tf32(acc[mt][nt], afh[mt], bfl[nt]);
                    mma_tf32(acc[mt][nt], afl[mt], bfh[nt]);
                    mma_tf32(acc[mt][nt], afh[mt], bfh[nt]);
                }
        }
        __syncthreads();
    }

    // transpose accumulators into C[b][u'-local]
#pragma unroll
    for (int nt = 0; nt < 2; ++nt)
#pragma unroll
        for (int cc = 0; cc < 2; ++cc) {
            int bl = wb * 16 + nt * 8 + 2 * tig + cc;
#pragma unroll
            for (int mt = 0; mt < 2; ++mt)
#pragma unroll
                for (int rr = 0; rr < 2; ++rr) {
                    int vl = wv * 32 + mt * 16 + g + rr * 8;
                    u.C[bl][vl] = acc[mt][nt][rr * 2 + cc];
                }
        }
    __syncthreads();

    // fused LSTM pointwise update: one (b, unit) per work item
    int base = u0 >> 2;                         // first unit in this tile
    int nU = (G4H - u0 >= 64) ? 16 : ((G4H - u0) >> 2);
    int total = 64 * nU;
    for (int e = tid; e < total; e += 256) {
        int bl, un;
        if (nU == 16) { bl = e >> 4; un = e & 15; }
        else          { bl = e / nU; un = e - bl * nU; }
        float gi = u.C[bl][un * 4 + 0] + sBias[un * 4 + 0];
        float gf = u.C[bl][un * 4 + 1] + sBias[un * 4 + 1];
        float gg = u.C[bl][un * 4 + 2] + sBias[un * 4 + 2];
        float go = u.C[bl][un * 4 + 3] + sBias[un * 4 + 3];
        int b = b0 + bl, unit = base + un;
        float cprev = g_c[b * HD + unit];
        float si = 1.f / (1.f + expf(-gi));
        float sf = 1.f / (1.f + expf(-gf));
        float so = 1.f / (1.f + expf(-go));
        float c = sf * cprev + si * tanhf(gg);
        float h = so * tanhf(c);
        g_c[b * HD + unit] = c;
        unsigned hh, hl; split1(h, hh, hl);
        g_h_hi[b * HD + unit] = hh;
        g_h_lo[b * HD + unit] = hl;
    }
}

// ---------------- G3: scores GEMM, 128v x 64b block, 32x32 warp tiles, cp.async pipeline ----------------
struct ScoresSM {
    unsigned AH[2][128][20];   // 20480 B
    unsigned AL[2][128][20];
    unsigned BH[2][64][20];    // 10240 B
    unsigned BL[2][64][20];
};  // 61440 bytes

#define SCORES_SMEM (61440 + 512)

__global__ __launch_bounds__(256) void scores_mma_kernel(
    const float* __restrict__ out_b, const unsigned* __restrict__ order_masks,
    float* __restrict__ sc_base, long long pitch, long long off, int t) {
    extern __shared__ __align__(16) unsigned char dsm[];
    ScoresSM* sm = (ScoresSM*)dsm;
    float (*C)[132] = (float(*)[132])dsm;               // aliases buffers after k-loop
    float* sOutB = (float*)(dsm + sizeof(ScoresSM));
    int tid = threadIdx.x;
    int v0 = blockIdx.x * 128, b0 = blockIdx.y * 64;
    int lane = tid & 31, warp = tid >> 5;
    int wv = warp & 3, wb = warp >> 2;                  // 4 v-quarters x 2 b-halves
    int g = lane >> 2, tig = lane & 3;

    if (tid < 128) {
        int v = v0 + tid;
        sOutB[tid] = (v < VV) ? out_b[v] : 0.f;
    }

    float acc[2][4][4];
#pragma unroll
    for (int mt = 0; mt < 2; ++mt)
#pragma unroll
        for (int nt = 0; nt < 4; ++nt)
#pragma unroll
            for (int q = 0; q < 4; ++q) acc[mt][nt][q] = 0.f;

    int arow = tid >> 1, akq = (tid & 1) * 8;   // A: 2 threads/row, 4 cpa16 each
    int brow = tid >> 2, bkq = (tid & 3) * 4;   // B: 4 threads/row, 2 cpa16 each
    int va = v0 + arow;
    size_t aoff = (va < VV) ? (size_t)va * HD : 0;
    int bb = b0 + brow;

    const int NIT = 13;                                  // 13*16 = 208 >= HD
    auto issue = [&](int it, int bi) {
        int k0 = it * 16;
        int kA0 = k0 + akq, kA1 = k0 + akq + 4, kB = k0 + bkq;
        bool pA0 = (va < VV) && (kA0 < HD);
        bool pA1 = (va < VV) && (kA1 < HD);
        bool pB  = (kB < HD);
        int cA0 = pA0 ? kA0 : 0, cA1 = pA1 ? kA1 : 0, cB = pB ? kB : 0;
        cpa16(&sm->AH[bi][arow][akq],     g_oW_hi + aoff + cA0, pA0);
        cpa16(&sm->AH[bi][arow][akq + 4], g_oW_hi + aoff + cA1, pA1);
        cpa16(&sm->AL[bi][arow][akq],     g_oW_lo + aoff + cA0, pA0);
        cpa16(&sm->AL[bi][arow][akq + 4], g_oW_lo + aoff + cA1, pA1);
        cpa16(&sm->BH[bi][brow][bkq],     g_h_hi + bb * HD + cB, pB);
        cpa16(&sm->BL[bi][brow][bkq],     g_h_lo + bb * HD + cB, pB);
    };

    issue(0, 0);
    asm volatile("cp.async.commit_group;");
    for (int it = 0; it < NIT; ++it) {
        if (it + 1 < NIT) issue(it + 1, (it + 1) & 1);
        asm volatile("cp.async.commit_group;");
        asm volatile("cp.async.wait_group 1;");
        __syncthreads();
        int bi = it & 1;
#pragma unroll
        for (int kk = 0; kk < 16; kk += 8) {
            unsigned afh[2][4], afl[2][4], bfh[4][2], bfl[4][2];
#pragma unroll
            for (int mt = 0; mt < 2; ++mt) {
                int r = wv * 32 + mt * 16 + g;
                afh[mt][0] = sm->AH[bi][r][kk + tig];
                afh[mt][1] = sm->AH[bi][r + 8][kk + tig];
                afh[mt][2] = sm->AH[bi][r][kk + tig + 4];
                afh[mt][3] = sm->AH[bi][r + 8][kk + tig + 4];
                afl[mt][0] = sm->AL[bi][r][kk + tig];
                afl[mt][1] = sm->AL[bi][r + 8][kk + tig];
                afl[mt][2] = sm->AL[bi][r][kk + tig + 4];
                afl[mt][3] = sm->AL[bi][r + 8][kk + tig + 4];
            }
#pragma unroll
            for (int nt = 0; nt < 4; ++nt) {
                int c = wb * 32 + nt * 8 + g;
                bfh[nt][0] = sm->BH[bi][c][kk + tig];
                bfh[nt][1] = sm->BH[bi][c][kk + tig + 4];
                bfl[nt][0] = sm->BL[bi][c][kk + tig];
                bfl[nt][1] = sm->BL[bi][c][kk + tig + 4];
            }
#pragma unroll
            for (int mt = 0; mt < 2; ++mt)
#pragma unroll
                for (int nt = 0; nt < 4; ++nt) {
                    mma_tf32(acc[mt][nt], afh[mt], bfl[nt]);
                    mma_tf32(acc[mt][nt], afl[mt], bfh[nt]);
                    mma_tf32(acc[mt][nt], afh[mt], bfh[nt]);
                }
        }
        __syncthreads();
    }

    // transpose accumulators through smem (aliases the now-idle buffers)
#pragma unroll
    for (int nt = 0; nt < 4; ++nt)
#pragma unroll
        for (int cc = 0; cc < 2; ++cc) {
            int bl = wb * 32 + nt * 8 + 2 * tig + cc;
#pragma unroll
            for (int mt = 0; mt < 2; ++mt)
#pragma unroll
                for (int rr = 0; rr < 2; ++rr) {
                    int vl = wv * 32 + mt * 16 + g + rr * 8;
                    C[bl][vl] = acc[mt][nt][rr * 2 + cc];
                }
        }
    __syncthreads();

    // coalesced float2 store with bias + mask
    for (int e = tid; e < 64 * 64; e += 256) {
        int bl = e >> 6, v2 = e & 63;
        int b = b0 + bl;
        int v = v0 + v2 * 2;
        if (v >= VV) continue;
        float2 c = *(float2*)&C[bl][v2 * 2];
        c.x += sOutB[v2 * 2];
        c.y += sOutB[v2 * 2 + 1];
        int inv = g_invalid[b];
        uint2 m2 = *(const uint2*)(order_masks + ((size_t)b * SS + t) * VV + v);
        bool ma = inv || (m2.x != 0u);
        bool mb = inv || (m2.y != 0u);
        float2 r;
        r.x = fminf(c.x, ma ? 9.0e8f : -1.0e8f);
        r.y = fminf(c.y, mb ? 9.0e8f : -1.0e8f);
        *(float2*)(sc_base + (long long)b * pitch + off + v) = r;
    }
}

// ---------------- G4: sample kernel — ballot-compacted gumbel argmax + finish ----------------
__device__ __forceinline__ float gproc(float sm, int vv, int b,
                                       unsigned k1t, unsigned k2t,
                                       float rb, unsigned long long& best) {
    uint2 r = tf2x32(k1t, k2t, 0u, (unsigned)(b * VV + vv));
    unsigned bits = r.x ^ r.y;
    float uf = __uint_as_float((bits >> 9) | 0x3F800000u) - 1.0f;
    uf = fmaxf(uf + 1.17549435e-38f, 1.17549435e-38f);
    float lnu_lo = fmaf((float)__float_as_int(uf), 8.2629582e-8f, -88.029694f);
    float e_min = -lnu_lo - 0.0605f;
    float gub = 3.0e38f;
    if (e_min > 1.17549435e-38f) {
        float lne_lo = fmaf((float)__float_as_int(e_min), 8.2629582e-8f, -88.029694f);
        gub = -lne_lo + 1.0e-3f;
    }
    if (sm + gub < rb) return -3.0e38f;
    float gum = -alogf(-alogf(uf));
    float cv = sm + gum;
    unsigned ub = __float_as_uint(cv);
    ub = (ub & 0x80000000u) ? ~ub : (ub | 0x80000000u);
    unsigned long long packed = ((unsigned long long)ub << 32) | (unsigned)(~(unsigned)vv);
    if (packed > best) best = packed;
    return cv;
}

__global__ __launch_bounds__(256) void sample_kernel(
    const float* __restrict__ sc_base, long long pitch, long long off,
    const float* __restrict__ order_embedding, float* __restrict__ idx_out, int t) {
    int b = blockIdx.x;
    const float* row = sc_base + (long long)b * pitch + off;
    int tid = threadIdx.x, warp = tid >> 5, lane = tid & 31;
    __shared__ unsigned short qv[8][64];
    __shared__ float qs[8][64];
    __shared__ unsigned long long wbest[8];
    __shared__ int sidx;
    unsigned k1t = g_keys[2 * t], k2t = g_keys[2 * t + 1];
    const int SEG = 1632;
    int s0 = warp * SEG;
    int s1 = min(s0 + SEG, VV);
    unsigned long long best = 0ULL;
    float rb = -3.0e38f;
    int qh = 0, qt = 0;

    for (int v0 = s0; v0 < s1; v0 += 32) {
        int v = v0 + lane;
        float sv = (v < s1) ? row[v] : -1.0e8f;
        bool cand = (v < s1) && (sv != -1.0e8f);
        unsigned mk = __ballot_sync(0xffffffffu, cand);
        int rank = __popc(mk & ((1u << lane) - 1u));
        if (cand) {
            int p = (qt + rank) & 63;
            qv[warp][p] = (unsigned short)v;
            qs[warp][p] = sv;
        }
        qt += __popc(mk);
        while (qt - qh >= 32) {
            __syncwarp();
            int p = (qh + lane) & 63;
            int vv = qv[warp][p];
            float smv = qs[warp][p];
            __syncwarp();
            qh += 32;
            float cv = gproc(smv, vv, b, k1t, k2t, rb, best);
#pragma unroll
            for (int o = 16; o; o >>= 1)
                cv = fmaxf(cv, __shfl_xor_sync(0xffffffffu, cv, o));
            rb = fmaxf(rb, cv);
        }
    }
    {
        int rem = qt - qh;
        __syncwarp();
        if (lane < rem) {
            int p = (qh + lane) & 63;
            int vv = qv[warp][p];
            float smv = qs[warp][p];
            (void)gproc(smv, vv, b, k1t, k2t, rb, best);
        }
    }
#pragma unroll
    for (int o = 16; o; o >>= 1) {
        unsigned long long ob = __shfl_xor_sync(0xffffffffu, best, o);
        if (ob > best) best = ob;
    }
    if (lane == 0) wbest[warp] = best;
    __syncthreads();
    if (tid == 0) {
        unsigned long long bb = 0ULL;
#pragma unroll
        for (int w = 0; w < 8; ++w) bb = (wbest[w] > bb) ? wbest[w] : bb;
        int idx = (bb == 0ULL) ? 0 : (int)(~(unsigned)(bb & 0xFFFFFFFFu));
        if (idx < 0) idx = 0;
        if (idx >= VV) idx = VV - 1;
        sidx = idx;
        if (idx_out) idx_out[b * SS + t] = (float)idx;
    }
    __syncthreads();
    if (tid < OED) {
        float val = order_embedding[(size_t)sidx * OED + tid];
        unsigned hh, hl; split1(val, hh, hl);
        g_oe_hi[b * OED + tid] = hh;
        g_oe_lo[b * OED + tid] = hl;
    }
}

// ---------------- launch ----------------
extern "C" void kernel_launch(void* const* d_in, const int* in_sizes, int n_in,
                              void* d_out, int out_size) {
    const float*    enc        = (const float*)d_in[0];
    const int*      loc_idxs   = (const int*)d_in[2];
    const unsigned* ord_masks  = (const unsigned*)d_in[3];
    const float*    power_1h   = (const float*)d_in[4];
    const float*    order_emb  = (const float*)d_in[5];
    const float*    power_W    = (const float*)d_in[6];
    const float*    power_b    = (const float*)d_in[7];
    const float*    W_ih       = (const float*)d_in[8];
    const float*    W_hh       = (const float*)d_in[9];
    const float*    b_ih       = (const float*)d_in[10];
    const float*    b_hh       = (const float*)d_in[11];
    const float*    out_W      = (const float*)d_in[12];
    const float*    out_b      = (const float*)d_in[13];
    const float*    master     = (const float*)d_in[14];

    float* out = (float*)d_out;
    float* idx_out = nullptr;
    float* scores_out = nullptr;
    const long long NSC = (long long)BB * SS * VV;
    if ((long long)out_size == NSC + (long long)BB * SS) { idx_out = out; scores_out = out + BB * SS; }
    else if ((long long)out_size == NSC)                 { scores_out = out; }
    else if (out_size == BB * SS)                        { idx_out = out; }
    else { scores_out = out; }

    float* g_scores_ptr = nullptr;
    cudaGetSymbolAddress((void**)&g_scores_ptr, g_scores);
    float*    sc_base = scores_out ? scores_out : g_scores_ptr;
    long long pitch   = scores_out ? (long long)SS * VV : (long long)VV;

    cudaFuncSetAttribute(scores_mma_kernel,
                         cudaFuncAttributeMaxDynamicSharedMemorySize, SCORES_SMEM);

    precompute_kernel<<<BB, 256>>>(enc, loc_idxs, power_1h, power_W, power_b, master);
    pack_gw_kernel<<<(G4H * KPAD + 255) / 256, 256>>>(W_ih, W_hh, b_ih, b_hh);
    pack_ow_kernel<<<(VV * HD + 255) / 256, 256>>>(out_W);

    dim3 g1grid((G4H + 63) / 64, BB / 64);           // 13 x 8 = 104 blocks
    dim3 g3grid((VV + 127) / 128, BB / 64);          // 102 x 8 = 816 blocks
    for (int t = 0; t < SS; ++t) {
        long long off = scores_out ? (long long)t * VV : 0;
        gates_fused_kernel<<<g1grid, 256>>>(t);
        scores_mma_kernel<<<g3grid, 256, SCORES_SMEM>>>(out_b, ord_masks, sc_base, pitch, off, t);
        sample_kernel<<<BB, 256>>>(sc_base, pitch, off, order_emb, idx_out, t);
    }
}

// round 16
// speedup vs baseline: 1.3379x; 1.1021x over previous
#include <cuda_runtime.h>

#define BB   512
#define SS   17
#define LL   81
#define VV   13030
#define ENCD 240
#define OED  80
#define PED  60
#define IND  380     // ENC + OE + PE
#define HD   200
#define G4H  800     // 4*H
#define KPAD 592     // 37*16, padded K for gates GEMM (reordered [h|enc|oe|pe|0])

// ---------------- scratch (static device globals; no allocation) ----------------
__device__ __align__(16) unsigned g_gW_hi[G4H * KPAD];   // permuted+packed gate weights
__device__ __align__(16) unsigned g_gW_lo[G4H * KPAD];
__device__ __align__(16) float    g_gbias[G4H];
__device__ __align__(16) unsigned g_oW_hi[VV * HD];
__device__ __align__(16) unsigned g_oW_lo[VV * HD];
__device__ __align__(16) unsigned g_le_hi[SS * BB * ENCD];
__device__ __align__(16) unsigned g_le_lo[SS * BB * ENCD];
__device__ __align__(16) unsigned g_pe_hi[BB * PED];
__device__ __align__(16) unsigned g_pe_lo[BB * PED];
__device__ __align__(16) unsigned g_h_hi[BB * HD];
__device__ __align__(16) unsigned g_h_lo[BB * HD];
__device__ __align__(16) unsigned g_oe_hi[BB * OED];
__device__ __align__(16) unsigned g_oe_lo[BB * OED];
__device__ __align__(16) float    g_c[BB * HD];
__device__ int      g_invalid[BB];
__device__ unsigned g_keys[2 * SS];
__device__ unsigned long long g_amax[BB];
__device__ __align__(16) float g_scores[BB * VV];        // scratch when no scores output

// ---------------- threefry2x32 (matches jax/_src/prng.py reference) ----------------
__device__ __forceinline__ uint2 tf2x32(unsigned k0, unsigned k1,
                                        unsigned x0, unsigned x1) {
    unsigned ks2 = k0 ^ k1 ^ 0x1BD11BDAu;
    x0 += k0; x1 += k1;
#define TFR(r) { x0 += x1; x1 = __funnelshift_l(x1, x1, (r)); x1 ^= x0; }
    TFR(13) TFR(15) TFR(26) TFR(6)
    x0 += k1; x1 += ks2 + 1u;
    TFR(17) TFR(29) TFR(16) TFR(24)
    x0 += ks2; x1 += k0 + 2u;
    TFR(13) TFR(15) TFR(26) TFR(6)
    x0 += k0; x1 += k1 + 3u;
    TFR(17) TFR(29) TFR(16) TFR(24)
    x0 += k1; x1 += ks2 + 4u;
    TFR(13) TFR(15) TFR(26) TFR(6)
    x0 += ks2; x1 += k0 + 5u;
#undef TFR
    return make_uint2(x0, x1);
}

// ---------------- accurate fp32 natural log (fdlibm e_logf; fast-math-proof) ----------------
__device__ __forceinline__ float alogf(float x) {
    int ib = __float_as_int(x);
    int k  = ((ib >> 23) & 0xFF) - 126;
    float m = __int_as_float((ib & 0x007FFFFF) | 0x3F000000);
    if (m < 0.70710678f) { m = m + m; k -= 1; }
    float f = m - 1.0f;
    float s = f / (2.0f + f);
    float z = s * s;
    float w = z * z;
    float t1 = w * (0.40000972152f + w * 0.24279078841f);
    float t2 = z * (0.66666662693f + w * 0.28498786688f);
    float R  = t2 + t1;
    float hfsq = 0.5f * f * f;
    float dk = (float)k;
    return dk * 0.69313812256f - ((hfsq - (s * (hfsq + R) + dk * 9.0580006145e-06f)) - f);
}

// ---------------- tf32 helpers ----------------
__device__ __forceinline__ unsigned f2tf32(float x) {
    unsigned r;
    asm("cvt.rna.tf32.f32 %0, %1;" : "=r"(r) : "f"(x));
    return r;
}
__device__ __forceinline__ void mma_tf32(float* c, const unsigned* a, const unsigned* b) {
    asm volatile(
        "mma.sync.aligned.m16n8k8.row.col.f32.tf32.tf32.f32 "
        "{%0,%1,%2,%3}, {%4,%5,%6,%7}, {%8,%9}, {%0,%1,%2,%3};\n"
        : "+f"(c[0]), "+f"(c[1]), "+f"(c[2]), "+f"(c[3])
        : "r"(a[0]), "r"(a[1]), "r"(a[2]), "r"(a[3]), "r"(b[0]), "r"(b[1]));
}
__device__ __forceinline__ void split1(float x, unsigned& hi, unsigned& lo) {
    hi = f2tf32(x);
    lo = f2tf32(x - __uint_as_float(hi));
}

// cp.async 16B with zero-fill predicate
__device__ __forceinline__ void cpa16(void* sdst, const void* gsrc, bool pred) {
    unsigned saddr = (unsigned)__cvta_generic_to_shared(sdst);
    int sz = pred ? 16 : 0;
    asm volatile("cp.async.cg.shared.global [%0], [%1], 16, %2;\n"
                 :: "r"(saddr), "l"(gsrc), "r"(sz));
}

// ---------------- gumbel candidate processing (identical math to prior rounds) ----------------
__device__ __forceinline__ float gproc(float sm, int vv, int b,
                                       unsigned k1t, unsigned k2t,
                                       float rb, unsigned long long& best) {
    uint2 r = tf2x32(k1t, k2t, 0u, (unsigned)(b * VV + vv));
    unsigned bits = r.x ^ r.y;
    float uf = __uint_as_float((bits >> 9) | 0x3F800000u) - 1.0f;
    uf = fmaxf(uf + 1.17549435e-38f, 1.17549435e-38f);
    float lnu_lo = fmaf((float)__float_as_int(uf), 8.2629582e-8f, -88.029694f);
    float e_min = -lnu_lo - 0.0605f;
    float gub = 3.0e38f;
    if (e_min > 1.17549435e-38f) {
        float lne_lo = fmaf((float)__float_as_int(e_min), 8.2629582e-8f, -88.029694f);
        gub = -lne_lo + 1.0e-3f;
    }
    if (sm + gub < rb) return -3.0e38f;
    float gum = -alogf(-alogf(uf));
    float cv = sm + gum;
    unsigned ub = __float_as_uint(cv);
    ub = (ub & 0x80000000u) ? ~ub : (ub | 0x80000000u);
    unsigned long long packed = ((unsigned long long)ub << 32) | (unsigned)(~(unsigned)vv);
    if (packed > best) best = packed;
    return cv;
}

// ---------------- pack kernels (run once per launch) ----------------
__global__ __launch_bounds__(256) void pack_gw_kernel(
    const float* __restrict__ W_ih, const float* __restrict__ W_hh,
    const float* __restrict__ b_ih, const float* __restrict__ b_hh) {
    int idx = blockIdx.x * blockDim.x + threadIdx.x;
    if (idx >= G4H * KPAD) return;
    int up = idx / KPAD, k = idx - up * KPAD;
    int orig = (up & 3) * HD + (up >> 2);
    float v = 0.f;
    if (k < HD)        v = W_hh[orig * HD + k];
    else if (k < 580)  v = W_ih[orig * IND + (k - HD)];
    unsigned hi, lo; split1(v, hi, lo);
    g_gW_hi[idx] = hi; g_gW_lo[idx] = lo;
    if (k == 0) g_gbias[up] = b_ih[orig] + b_hh[orig];
}

__global__ __launch_bounds__(256) void pack_ow_kernel(const float* __restrict__ out_W) {
    int idx = blockIdx.x * blockDim.x + threadIdx.x;
    if (idx >= VV * HD) return;
    unsigned hi, lo; split1(out_W[idx], hi, lo);
    g_oW_hi[idx] = hi; g_oW_lo[idx] = lo;
}

// ---------------- kernel A: precompute loc_enc(split)/power_emb(split)/state/keys ----------------
__global__ __launch_bounds__(256) void precompute_kernel(
    const float* __restrict__ enc, const int* __restrict__ loc_idxs,
    const float* __restrict__ power_1h, const float* __restrict__ power_W,
    const float* __restrict__ power_b, const float* __restrict__ master) {
    __shared__ float sM[LL * LL];
    __shared__ float sAl[SS][LL];
    __shared__ float sDen[SS];
    __shared__ int   sLoc[LL];
    int b = blockIdx.x;
    int tid = threadIdx.x;

    for (int i = tid; i < LL * LL; i += 256) sM[i] = master[i];
    if (tid < LL) sLoc[tid] = loc_idxs[b * LL + tid];
    for (int i = tid; i < HD; i += 256) {
        g_h_hi[b * HD + i] = 0u; g_h_lo[b * HD + i] = 0u; g_c[b * HD + i] = 0.f;
    }
    for (int i = tid; i < OED; i += 256) { g_oe_hi[b * OED + i] = 0u; g_oe_lo[b * OED + i] = 0u; }
    if (tid == 0) g_amax[b] = 0ULL;
    if (tid < PED) {
        float acc = power_b[tid];
        for (int j = 0; j < 7; ++j) acc += power_1h[b * 7 + j] * power_W[tid * 7 + j];
        unsigned hi, lo; split1(acc, hi, lo);
        g_pe_hi[b * PED + tid] = hi; g_pe_lo[b * PED + tid] = lo;
    }
    if (b == 0 && tid < SS) {
        uint2 r = tf2x32(0u, 42u, 0u, (unsigned)tid);
        g_keys[2 * tid]     = r.x;
        g_keys[2 * tid + 1] = r.y;
    }
    __syncthreads();

    if (tid == 0) {
        int any = 0;
        for (int l = 0; l < LL; ++l) any |= (sLoc[l] != -1);
        g_invalid[b] = !any;
    }
    for (int e = tid; e < SS * LL; e += 256) {
        int t = e / LL, j = e % LL;
        float a = 0.f;
        for (int l = 0; l < LL; ++l) {
            int li = sLoc[l];
            if (li == t || li == -2) a += sM[l * LL + j];
        }
        sAl[t][j] = a;
    }
    __syncthreads();
    if (tid < SS) {
        float d = 0.f;
        for (int j = 0; j < LL; ++j) d += sAl[tid][j];
        sDen[tid] = d;
    }
    __syncthreads();
    for (int e = tid; e < SS * LL; e += 256) {
        int t = e / LL, j = e % LL;
        float d = sDen[t];
        sAl[t][j] = (d != 0.f) ? sAl[t][j] / d : 0.f;
    }
    __syncthreads();
    if (tid < ENCD) {
        float acc[SS];
#pragma unroll
        for (int t = 0; t < SS; ++t) acc[t] = 0.f;
        for (int l = 0; l < LL; ++l) {
            float v = enc[((size_t)b * LL + l) * ENCD + tid];
#pragma unroll
            for (int t = 0; t < SS; ++t) acc[t] += sAl[t][l] * v;
        }
#pragma unroll
        for (int t = 0; t < SS; ++t) {
            unsigned hi, lo; split1(acc[t], hi, lo);
            size_t o = ((size_t)t * BB + b) * ENCD + tid;
            g_le_hi[o] = hi; g_le_lo[o] = lo;
        }
    }
}

// ---------------- G1: fused gates GEMM + LSTM update (64x64 tiles, 3-stage cp.async pipeline) ----------------
struct GatesSM {
    union {
        struct {
            unsigned AH[3][64][20];
            unsigned AL[3][64][20];
            unsigned BH[3][64][20];
            unsigned BL[3][64][20];
        } p;
        float C[64][68];
    };
};

__global__ __launch_bounds__(256) void gates_fused_kernel(int t) {
    __shared__ GatesSM u;
    __shared__ float sBias[64];
    int tid = threadIdx.x;
    int u0 = blockIdx.x * 64, b0 = blockIdx.y * 64;
    int lane = tid & 31, warp = tid >> 5;
    int wv = warp & 1, wb = warp >> 1;         // 2 (rows) x 4 (cols)
    int g = lane >> 2, tig = lane & 3;

    if (tid < 64) {
        int up = u0 + tid;
        sBias[tid] = (up < G4H) ? g_gbias[up] : 0.f;
    }

    float acc[2][2][4];
#pragma unroll
    for (int mt = 0; mt < 2; ++mt)
#pragma unroll
        for (int nt = 0; nt < 2; ++nt)
#pragma unroll
            for (int q = 0; q < 4; ++q) acc[mt][nt][q] = 0.f;

    int arow = tid >> 2, akp = (tid & 3) * 4;
    int brow = arow,    bkp = akp;
    int up = u0 + arow;
    bool pA = (up < G4H);
    size_t abase = (size_t)(pA ? up : 0) * KPAD;
    int bb = b0 + brow;
    const size_t le_row = (size_t)t * BB * ENCD + (size_t)bb * ENCD;

    const int NIT = KPAD / 16;                 // 37
    auto issue = [&](int it, int bi) {
        int k0 = it * 16;
        cpa16(&u.p.AH[bi][arow][akp], g_gW_hi + abase + k0 + akp, pA);
        cpa16(&u.p.AL[bi][arow][akp], g_gW_lo + abase + k0 + akp, pA);
        int k = k0 + bkp;
        const unsigned *sh = g_h_hi, *sl = g_h_lo;
        bool pB = true;
        if (k < HD)                   { sh = g_h_hi + bb * HD + k;            sl = g_h_lo + bb * HD + k; }
        else if (k < HD + ENCD)       { sh = g_le_hi + le_row + (k - HD);     sl = g_le_lo + le_row + (k - HD); }
        else if (k < HD + ENCD + OED) { sh = g_oe_hi + bb * OED + (k - 440);  sl = g_oe_lo + bb * OED + (k - 440); }
        else if (k < 580)             { sh = g_pe_hi + bb * PED + (k - 520);  sl = g_pe_lo + bb * PED + (k - 520); }
        else                          { pB = false; }
        cpa16(&u.p.BH[bi][brow][bkp], sh, pB);
        cpa16(&u.p.BL[bi][brow][bkp], sl, pB);
    };

    issue(0, 0);
    asm volatile("cp.async.commit_group;");
    issue(1, 1);
    asm volatile("cp.async.commit_group;");
    for (int it = 0; it < NIT; ++it) {
        if (it + 2 < NIT) {
            issue(it + 2, (it + 2) % 3);
            asm volatile("cp.async.commit_group;");
            asm volatile("cp.async.wait_group 2;");
        } else {
            asm volatile("cp.async.wait_group 0;");
        }
        __syncthreads();
        int bi = it % 3;
#pragma unroll
        for (int kk = 0; kk < 16; kk += 8) {
            unsigned afh[2][4], afl[2][4], bfh[2][2], bfl[2][2];
#pragma unroll
            for (int mt = 0; mt < 2; ++mt) {
                int r = wv * 32 + mt * 16 + g;
                afh[mt][0] = u.p.AH[bi][r][kk + tig];
                afh[mt][1] = u.p.AH[bi][r + 8][kk + tig];
                afh[mt][2] = u.p.AH[bi][r][kk + tig + 4];
                afh[mt][3] = u.p.AH[bi][r + 8][kk + tig + 4];
                afl[mt][0] = u.p.AL[bi][r][kk + tig];
                afl[mt][1] = u.p.AL[bi][r + 8][kk + tig];
                afl[mt][2] = u.p.AL[bi][r][kk + tig + 4];
                afl[mt][3] = u.p.AL[bi][r + 8][kk + tig + 4];
            }
#pragma unroll
            for (int nt = 0; nt < 2; ++nt) {
                int c = wb * 16 + nt * 8 + g;
                bfh[nt][0] = u.p.BH[bi][c][kk + tig];
                bfh[nt][1] = u.p.BH[bi][c][kk + tig + 4];
                bfl[nt][0] = u.p.BL[bi][c][kk + tig];
                bfl[nt][1] = u.p.BL[bi][c][kk + tig + 4];
            }
#pragma unroll
            for (int mt = 0; mt < 2; ++mt)
#pragma unroll
                for (int nt = 0; nt < 2; ++nt) {
                    mma_tf32(acc[mt][nt], afh[mt], bfl[nt]);
                    mma_tf32(acc[mt][nt], afl[mt], bfh[nt]);
                    mma_tf32(acc[mt][nt], afh[mt], bfh[nt]);
                }
        }
        __syncthreads();
    }

    // transpose accumulators into C[b][u'-local]
#pragma unroll
    for (int nt = 0; nt < 2; ++nt)
#pragma unroll
        for (int cc = 0; cc < 2; ++cc) {
            int bl = wb * 16 + nt * 8 + 2 * tig + cc;
#pragma unroll
            for (int mt = 0; mt < 2; ++mt)
#pragma unroll
                for (int rr = 0; rr < 2; ++rr) {
                    int vl = wv * 32 + mt * 16 + g + rr * 8;
                    u.C[bl][vl] = acc[mt][nt][rr * 2 + cc];
                }
        }
    __syncthreads();

    // fused LSTM pointwise update
    int base = u0 >> 2;
    int nU = (G4H - u0 >= 64) ? 16 : ((G4H - u0) >> 2);
    int total = 64 * nU;
    for (int e = tid; e < total; e += 256) {
        int bl, un;
        if (nU == 16) { bl = e >> 4; un = e & 15; }
        else          { bl = e / nU; un = e - bl * nU; }
        float gi = u.C[bl][un * 4 + 0] + sBias[un * 4 + 0];
        float gf = u.C[bl][un * 4 + 1] + sBias[un * 4 + 1];
        float gg = u.C[bl][un * 4 + 2] + sBias[un * 4 + 2];
        float go = u.C[bl][un * 4 + 3] + sBias[un * 4 + 3];
        int b = b0 + bl, unit = base + un;
        float cprev = g_c[b * HD + unit];
        float si = 1.f / (1.f + expf(-gi));
        float sf = 1.f / (1.f + expf(-gf));
        float so = 1.f / (1.f + expf(-go));
        float c = sf * cprev + si * tanhf(gg);
        float h = so * tanhf(c);
        g_c[b * HD + unit] = c;
        unsigned hh, hl; split1(h, hh, hl);
        g_h_hi[b * HD + unit] = hh;
        g_h_lo[b * HD + unit] = hl;
    }
}

// ---------------- G3: scores GEMM + fused gumbel-argmax epilogue ----------------
struct ScoresSM {
    unsigned AH[2][128][20];   // 20480 B
    unsigned AL[2][128][20];
    unsigned BH[2][64][20];    // 10240 B
    unsigned BL[2][64][20];
};  // 61440 bytes

// layout: [0,61440) ScoresSM / C alias; [61440,61952) sOutB(128 f);
// [61952,64000) qv (8 warps x 128 u16); [64000,68096) qs (8 x 128 f)
#define SCORES_SMEM 68096

__global__ __launch_bounds__(256) void scores_mma_kernel(
    const float* __restrict__ out_b, const unsigned* __restrict__ order_masks,
    float* __restrict__ sc_base, long long pitch, long long off, int t) {
    extern __shared__ __align__(16) unsigned char dsm[];
    ScoresSM* sm = (ScoresSM*)dsm;
    float (*C)[132] = (float(*)[132])dsm;               // aliases buffers after k-loop
    float* sOutB = (float*)(dsm + 61440);
    unsigned short* qv = (unsigned short*)(dsm + 61952);
    float* qs = (float*)(dsm + 64000);
    int tid = threadIdx.x;
    int v0 = blockIdx.x * 128, b0 = blockIdx.y * 64;
    int lane = tid & 31, warp = tid >> 5;
    int wv = warp & 3, wb = warp >> 2;                  // 4 v-quarters x 2 b-halves
    int g = lane >> 2, tig = lane & 3;

    if (tid < 128) {
        int v = v0 + tid;
        sOutB[tid] = (v < VV) ? out_b[v] : 0.f;
    }

    float acc[2][4][4];
#pragma unroll
    for (int mt = 0; mt < 2; ++mt)
#pragma unroll
        for (int nt = 0; nt < 4; ++nt)
#pragma unroll
            for (int q = 0; q < 4; ++q) acc[mt][nt][q] = 0.f;

    int arow = tid >> 1, akq = (tid & 1) * 8;
    int brow = tid >> 2, bkq = (tid & 3) * 4;
    int va = v0 + arow;
    size_t aoff = (va < VV) ? (size_t)va * HD : 0;
    int bb = b0 + brow;

    const int NIT = 13;
    auto issue = [&](int it, int bi) {
        int k0 = it * 16;
        int kA0 = k0 + akq, kA1 = k0 + akq + 4, kB = k0 + bkq;
        bool pA0 = (va < VV) && (kA0 < HD);
        bool pA1 = (va < VV) && (kA1 < HD);
        bool pB  = (kB < HD);
        int cA0 = pA0 ? kA0 : 0, cA1 = pA1 ? kA1 : 0, cB = pB ? kB : 0;
        cpa16(&sm->AH[bi][arow][akq],     g_oW_hi + aoff + cA0, pA0);
        cpa16(&sm->AH[bi][arow][akq + 4], g_oW_hi + aoff + cA1, pA1);
        cpa16(&sm->AL[bi][arow][akq],     g_oW_lo + aoff + cA0, pA0);
        cpa16(&sm->AL[bi][arow][akq + 4], g_oW_lo + aoff + cA1, pA1);
        cpa16(&sm->BH[bi][brow][bkq],     g_h_hi + bb * HD + cB, pB);
        cpa16(&sm->BL[bi][brow][bkq],     g_h_lo + bb * HD + cB, pB);
    };

    issue(0, 0);
    asm volatile("cp.async.commit_group;");
    for (int it = 0; it < NIT; ++it) {
        if (it + 1 < NIT) issue(it + 1, (it + 1) & 1);
        asm volatile("cp.async.commit_group;");
        asm volatile("cp.async.wait_group 1;");
        __syncthreads();
        int bi = it & 1;
#pragma unroll
        for (int kk = 0; kk < 16; kk += 8) {
            unsigned afh[2][4], afl[2][4], bfh[4][2], bfl[4][2];
#pragma unroll
            for (int mt = 0; mt < 2; ++mt) {
                int r = wv * 32 + mt * 16 + g;
                afh[mt][0] = sm->AH[bi][r][kk + tig];
                afh[mt][1] = sm->AH[bi][r + 8][kk + tig];
                afh[mt][2] = sm->AH[bi][r][kk + tig + 4];
                afh[mt][3] = sm->AH[bi][r + 8][kk + tig + 4];
                afl[mt][0] = sm->AL[bi][r][kk + tig];
                afl[mt][1] = sm->AL[bi][r + 8][kk + tig];
                afl[mt][2] = sm->AL[bi][r][kk + tig + 4];
                afl[mt][3] = sm->AL[bi][r + 8][kk + tig + 4];
            }
#pragma unroll
            for (int nt = 0; nt < 4; ++nt) {
                int c = wb * 32 + nt * 8 + g;
                bfh[nt][0] = sm->BH[bi][c][kk + tig];
                bfh[nt][1] = sm->BH[bi][c][kk + tig + 4];
                bfl[nt][0] = sm->BL[bi][c][kk + tig];
                bfl[nt][1] = sm->BL[bi][c][kk + tig + 4];
            }
#pragma unroll
            for (int mt = 0; mt < 2; ++mt)
#pragma unroll
                for (int nt = 0; nt < 4; ++nt) {
                    mma_tf32(acc[mt][nt], afh[mt], bfl[nt]);
                    mma_tf32(acc[mt][nt], afl[mt], bfh[nt]);
                    mma_tf32(acc[mt][nt], afh[mt], bfh[nt]);
                }
        }
        __syncthreads();
    }

    // transpose accumulators through smem (aliases the now-idle buffers)
#pragma unroll
    for (int nt = 0; nt < 4; ++nt)
#pragma unroll
        for (int cc = 0; cc < 2; ++cc) {
            int bl = wb * 32 + nt * 8 + 2 * tig + cc;
#pragma unroll
            for (int mt = 0; mt < 2; ++mt)
#pragma unroll
                for (int rr = 0; rr < 2; ++rr) {
                    int vl = wv * 32 + mt * 16 + g + rr * 8;
                    C[bl][vl] = acc[mt][nt][rr * 2 + cc];
                }
        }
    __syncthreads();

    // coalesced float2 store with bias + mask; masked value written back to C for the scan
    for (int e = tid; e < 64 * 64; e += 256) {
        int bl = e >> 6, v2 = e & 63;
        int b = b0 + bl;
        int v = v0 + v2 * 2;
        if (v >= VV) continue;
        float2 c = *(float2*)&C[bl][v2 * 2];
        c.x += sOutB[v2 * 2];
        c.y += sOutB[v2 * 2 + 1];
        int inv = g_invalid[b];
        uint2 m2 = *(const uint2*)(order_masks + ((size_t)b * SS + t) * VV + v);
        bool ma = inv || (m2.x != 0u);
        bool mb = inv || (m2.y != 0u);
        float2 r;
        r.x = fminf(c.x, ma ? 9.0e8f : -1.0e8f);
        r.y = fminf(c.y, mb ? 9.0e8f : -1.0e8f);
        *(float2*)&C[bl][v2 * 2] = r;
        *(float2*)(sc_base + (long long)b * pitch + off + v) = r;
    }
    __syncthreads();

    // fused gumbel-argmax scan: warp w owns rows [8w, 8w+8)
    unsigned k1t = g_keys[2 * t], k2t = g_keys[2 * t + 1];
    unsigned short* myqv = qv + warp * 128;
    float* myqs = qs + warp * 128;
#pragma unroll 1
    for (int r8 = 0; r8 < 8; ++r8) {
        int bl = warp * 8 + r8;
        int b = b0 + bl;
        // compact candidates of this row into the warp queue
        int qt = 0;
#pragma unroll
        for (int cch = 0; cch < 4; ++cch) {
            int vl = cch * 32 + lane;
            float sv = C[bl][vl];
            bool cand = (v0 + vl < VV) && (sv != -1.0e8f);
            unsigned mk = __ballot_sync(0xffffffffu, cand);
            int rank = __popc(mk & ((1u << lane) - 1u));
            if (cand) {
                myqv[qt + rank] = (unsigned short)vl;
                myqs[qt + rank] = sv;
            }
            qt += __popc(mk);
        }
        __syncwarp();
        // process queue with full warps (exact path; rb=-inf so identical values)
        unsigned long long best = 0ULL;
        for (int base = 0; base < qt; base += 32) {
            int i = base + lane;
            if (i < qt) {
                int vvg = v0 + (int)myqv[i];
                float smv = myqs[i];
                (void)gproc(smv, vvg, b, k1t, k2t, -3.0e38f, best);
            }
        }
#pragma unroll
        for (int o = 16; o; o >>= 1) {
            unsigned long long ob = __shfl_xor_sync(0xffffffffu, best, o);
            if (ob > best) best = ob;
        }
        if (lane == 0 && best) atomicMax(&g_amax[b], best);
        __syncwarp();
    }
}

// ---------------- G4: finish kernel — idx output + order embedding, reset slot ----------------
__global__ void finish_kernel(const float* __restrict__ order_embedding,
                              float* __restrict__ idx_out, int t) {
    int b = blockIdx.x;
    __shared__ int sidx;
    if (threadIdx.x == 0) {
        unsigned long long p = g_amax[b];
        int idx = (p == 0ULL) ? 0 : (int)(~(unsigned)(p & 0xFFFFFFFFu));
        if (idx < 0) idx = 0;
        if (idx >= VV) idx = VV - 1;
        sidx = idx;
        g_amax[b] = 0ULL;
        if (idx_out) idx_out[b * SS + t] = (float)idx;
    }
    __syncthreads();
    if (threadIdx.x < OED) {
        float val = order_embedding[(size_t)sidx * OED + threadIdx.x];
        unsigned hh, hl; split1(val, hh, hl);
        g_oe_hi[b * OED + threadIdx.x] = hh;
        g_oe_lo[b * OED + threadIdx.x] = hl;
    }
}

// ---------------- launch ----------------
extern "C" void kernel_launch(void* const* d_in, const int* in_sizes, int n_in,
                              void* d_out, int out_size) {
    const float*    enc        = (const float*)d_in[0];
    const int*      loc_idxs   = (const int*)d_in[2];
    const unsigned* ord_masks  = (const unsigned*)d_in[3];
    const float*    power_1h   = (const float*)d_in[4];
    const float*    order_emb  = (const float*)d_in[5];
    const float*    power_W    = (const float*)d_in[6];
    const float*    power_b    = (const float*)d_in[7];
    const float*    W_ih       = (const float*)d_in[8];
    const float*    W_hh       = (const float*)d_in[9];
    const float*    b_ih       = (const float*)d_in[10];
    const float*    b_hh       = (const float*)d_in[11];
    const float*    out_W      = (const float*)d_in[12];
    const float*    out_b      = (const float*)d_in[13];
    const float*    master     = (const float*)d_in[14];

    float* out = (float*)d_out;
    float* idx_out = nullptr;
    float* scores_out = nullptr;
    const long long NSC = (long long)BB * SS * VV;
    if ((long long)out_size == NSC + (long long)BB * SS) { idx_out = out; scores_out = out + BB * SS; }
    else if ((long long)out_size == NSC)                 { scores_out = out; }
    else if (out_size == BB * SS)                        { idx_out = out; }
    else { scores_out = out; }

    float* g_scores_ptr = nullptr;
    cudaGetSymbolAddress((void**)&g_scores_ptr, g_scores);
    float*    sc_base = scores_out ? scores_out : g_scores_ptr;
    long long pitch   = scores_out ? (long long)SS * VV : (long long)VV;

    cudaFuncSetAttribute(scores_mma_kernel,
                         cudaFuncAttributeMaxDynamicSharedMemorySize, SCORES_SMEM);

    precompute_kernel<<<BB, 256>>>(enc, loc_idxs, power_1h, power_W, power_b, master);
    pack_gw_kernel<<<(G4H * KPAD + 255) / 256, 256>>>(W_ih, W_hh, b_ih, b_hh);
    pack_ow_kernel<<<(VV * HD + 255) / 256, 256>>>(out_W);

    dim3 g1grid((G4H + 63) / 64, BB / 64);           // 13 x 8 = 104 blocks
    dim3 g3grid((VV + 127) / 128, BB / 64);          // 102 x 8 = 816 blocks
    for (int t = 0; t < SS; ++t) {
        long long off = scores_out ? (long long)t * VV : 0;
        gates_fused_kernel<<<g1grid, 256>>>(t);
        scores_mma_kernel<<<g3grid, 256, SCORES_SMEM>>>(out_b, ord_masks, sc_base, pitch, off, t);
        finish_kernel<<<BB, 128>>>(order_emb, idx_out, t);
    }
}